// round 1
// baseline (speedup 1.0000x reference)
#include <cuda_runtime.h>
#include <cuda_bf16.h>

// ---------------------------------------------------------------------------
// GNN_6837587935613: RGCN(mean, R=8) -> TransformerConv(1 head) -> BN+LeakyReLU
// N=50000, E=800000, G_DIM=512, H1=H2=128, R=8
// ---------------------------------------------------------------------------

#define NN   50000
#define EE   800000
#define GD   512
#define HD   128
#define RR   8

// ---- scratch (device globals; allocation inside kernel_launch is banned) ----
__device__ float4   g_xW[(size_t)NN * 256];   // [N, R*128] = 204.8 MB
__device__ float4   g_h [(size_t)NN * 32];    // [N, 128]
__device__ float4   g_q [(size_t)NN * 32];
__device__ float4   g_k [(size_t)NN * 32];
__device__ float4   g_v [(size_t)NN * 32];
__device__ int      g_cnt[NN * RR];
__device__ float    g_score[EE];
__device__ unsigned g_smax[NN];
__device__ float    g_ssum[NN];
__device__ float    g_bnsum[HD];
__device__ float    g_bnsq[HD];
__device__ float    g_scale[HD];
__device__ float    g_shift[HD];
__device__ int      g_idx64;

// ---- index dtype handling (jax may emit int32 despite jnp.int64 request) ----
__device__ __forceinline__ int ldidx(const void* p, long i) {
    return g_idx64 ? (int)((const long long*)p)[i] : ((const int*)p)[i];
}

__global__ void detect_k(const unsigned* __restrict__ w) {
    if (blockIdx.x == 0 && threadIdx.x == 0) {
        int is64 = 1;
        for (int i = 0; i < 32; i++)
            if (w[2 * i + 1] != 0u) { is64 = 0; break; }
        g_idx64 = is64;
    }
}

__global__ void init_k() {
    int i = blockIdx.x * blockDim.x + threadIdx.x;
    if (i < NN * RR) g_cnt[i] = 0;
    if (i < NN) { g_ssum[i] = 0.f; g_smax[i] = 0u; }
    if (i < HD) { g_bnsum[i] = 0.f; g_bnsq[i] = 0.f; }
}

__global__ void count_k(const void* __restrict__ ei, const void* __restrict__ et) {
    int e = blockIdx.x * blockDim.x + threadIdx.x;
    if (e >= EE) return;
    int dst = ldidx(ei, (long)EE + e);
    int r   = ldidx(et, e);
    atomicAdd(&g_cnt[dst * RR + r], 1);
}

// ---------------------------------------------------------------------------
// fp32 tiled GEMM: C[M, z-strided cols] = A[M,K] @ B[K,128] (+bias)
// grid = (128/64, ceil(M/64), Z); B += z*bStrideZ; C col base = z*128 + bx*64
// ---------------------------------------------------------------------------
__global__ __launch_bounds__(256) void gemm_k(
    const float* __restrict__ A, const float* __restrict__ Bbase,
    float* __restrict__ C, const float* __restrict__ bias,
    int M, int K, int ldc, long bStrideZ)
{
    __shared__ float As[16][65];
    __shared__ float Bs[16][68];
    const int bx = blockIdx.x, by = blockIdx.y, bz = blockIdx.z;
    const float* B = Bbase + (long)bz * bStrideZ;
    const int row0  = by * 64;
    const int colB0 = bx * 64;
    const int colC0 = bz * 128 + colB0;
    const int tid = threadIdx.x;
    const int tx = tid & 15, ty = tid >> 4;

    float acc[4][4];
#pragma unroll
    for (int i = 0; i < 4; i++)
#pragma unroll
        for (int j = 0; j < 4; j++) acc[i][j] = 0.f;

    for (int k0 = 0; k0 < K; k0 += 16) {
#pragma unroll
        for (int l = 0; l < 4; l++) {
            int lin = tid + l * 256;
            int m = lin >> 4, kk = lin & 15;
            int r = row0 + m;
            As[kk][m] = (r < M) ? A[(long)r * K + k0 + kk] : 0.f;
        }
#pragma unroll
        for (int l = 0; l < 4; l++) {
            int lin = tid + l * 256;
            int i = lin >> 6, j = lin & 63;
            Bs[i][j] = B[(long)(k0 + i) * 128 + colB0 + j];
        }
        __syncthreads();
#pragma unroll
        for (int kk = 0; kk < 16; kk++) {
            float a0 = As[kk][ty * 4 + 0], a1 = As[kk][ty * 4 + 1];
            float a2 = As[kk][ty * 4 + 2], a3 = As[kk][ty * 4 + 3];
            float b0 = Bs[kk][tx * 4 + 0], b1 = Bs[kk][tx * 4 + 1];
            float b2 = Bs[kk][tx * 4 + 2], b3 = Bs[kk][tx * 4 + 3];
            acc[0][0] += a0 * b0; acc[0][1] += a0 * b1; acc[0][2] += a0 * b2; acc[0][3] += a0 * b3;
            acc[1][0] += a1 * b0; acc[1][1] += a1 * b1; acc[1][2] += a1 * b2; acc[1][3] += a1 * b3;
            acc[2][0] += a2 * b0; acc[2][1] += a2 * b1; acc[2][2] += a2 * b2; acc[2][3] += a2 * b3;
            acc[3][0] += a3 * b0; acc[3][1] += a3 * b1; acc[3][2] += a3 * b2; acc[3][3] += a3 * b3;
        }
        __syncthreads();
    }

#pragma unroll
    for (int i = 0; i < 4; i++) {
        int r = row0 + ty * 4 + i;
        if (r >= M) continue;
#pragma unroll
        for (int j = 0; j < 4; j++) {
            float v = acc[i][j];
            if (bias) v += bias[colB0 + tx * 4 + j];
            C[(long)r * ldc + colC0 + tx * 4 + j] = v;
        }
    }
}

// ---- RGCN aggregation: warp per edge, h[dst] += xW[src, etype] / cnt ----
__global__ void agg1_k(const void* __restrict__ ei, const void* __restrict__ et) {
    long w = ((long)blockIdx.x * blockDim.x + threadIdx.x) >> 5;
    int lane = threadIdx.x & 31;
    if (w >= EE) return;
    int src = ldidx(ei, w);
    int dst = ldidx(ei, (long)EE + w);
    int r   = ldidx(et, w);
    float inv = 1.0f / (float)g_cnt[dst * RR + r];
    float4 m = g_xW[(long)src * 256 + r * 32 + lane];
    float* hb = (float*)g_h + (long)dst * 128 + lane * 4;
    atomicAdd(hb + 0, m.x * inv);
    atomicAdd(hb + 1, m.y * inv);
    atomicAdd(hb + 2, m.z * inv);
    atomicAdd(hb + 3, m.w * inv);
}

// ---- attention score + segment max (monotone float<->uint mapping) ----
__device__ __forceinline__ unsigned f2o(float f) {
    unsigned u = __float_as_uint(f);
    return (u & 0x80000000u) ? ~u : (u | 0x80000000u);
}
__device__ __forceinline__ float o2f(unsigned u) {
    return (u & 0x80000000u) ? __uint_as_float(u & 0x7fffffffu) : __uint_as_float(~u);
}

__global__ void score_k(const void* __restrict__ ei) {
    long w = ((long)blockIdx.x * blockDim.x + threadIdx.x) >> 5;
    int lane = threadIdx.x & 31;
    if (w >= EE) return;
    int src = ldidx(ei, w);
    int dst = ldidx(ei, (long)EE + w);
    float4 qd = g_q[(long)dst * 32 + lane];
    float4 ks = g_k[(long)src * 32 + lane];
    float p = qd.x * ks.x + qd.y * ks.y + qd.z * ks.z + qd.w * ks.w;
#pragma unroll
    for (int off = 16; off; off >>= 1) p += __shfl_down_sync(0xffffffffu, p, off);
    if (lane == 0) {
        float s = p * 0.08838834764831845f;  // 1/sqrt(128)
        g_score[w] = s;
        atomicMax(&g_smax[dst], f2o(s));
    }
}

__global__ void expsum_k(const void* __restrict__ ei) {
    int e = blockIdx.x * blockDim.x + threadIdx.x;
    if (e >= EE) return;
    int dst = ldidx(ei, (long)EE + e);
    float m = o2f(g_smax[dst]);
    float ex = expf(g_score[e] - m);
    g_score[e] = ex;
    atomicAdd(&g_ssum[dst], ex);
}

__global__ void agg2_k(const void* __restrict__ ei, float* __restrict__ out) {
    long w = ((long)blockIdx.x * blockDim.x + threadIdx.x) >> 5;
    int lane = threadIdx.x & 31;
    if (w >= EE) return;
    int src = ldidx(ei, w);
    int dst = ldidx(ei, (long)EE + w);
    float alpha = g_score[w] / fmaxf(g_ssum[dst], 1e-16f);
    float4 vv = g_v[(long)src * 32 + lane];
    float* ob = out + (long)dst * 128 + lane * 4;
    atomicAdd(ob + 0, alpha * vv.x);
    atomicAdd(ob + 1, alpha * vv.y);
    atomicAdd(ob + 2, alpha * vv.z);
    atomicAdd(ob + 3, alpha * vv.w);
}

// ---- batch norm ----
__global__ void bnstats_k(const float* __restrict__ x) {
    __shared__ float ssum[HD], ssq[HD];
    if (threadIdx.x < HD) { ssum[threadIdx.x] = 0.f; ssq[threadIdx.x] = 0.f; }
    __syncthreads();
    const long total = (long)NN * HD;
    for (long i = (long)blockIdx.x * blockDim.x + threadIdx.x; i < total;
         i += (long)gridDim.x * blockDim.x) {
        float v = x[i];
        int c = (int)(i & 127);
        atomicAdd(&ssum[c], v);
        atomicAdd(&ssq[c], v * v);
    }
    __syncthreads();
    if (threadIdx.x < HD) {
        atomicAdd(&g_bnsum[threadIdx.x], ssum[threadIdx.x]);
        atomicAdd(&g_bnsq[threadIdx.x], ssq[threadIdx.x]);
    }
}

__global__ void bnfinal_k(const float* __restrict__ gamma, const float* __restrict__ beta) {
    int c = threadIdx.x;
    float mu  = g_bnsum[c] * (1.0f / NN);
    float var = g_bnsq[c] * (1.0f / NN) - mu * mu;
    var = fmaxf(var, 0.f);
    float inv = 1.0f / sqrtf(var + 1e-5f);
    float sc = gamma[c] * inv;
    g_scale[c] = sc;
    g_shift[c] = beta[c] - mu * sc;
}

__global__ void bnapply_k(float* __restrict__ out) {
    long i = (long)blockIdx.x * blockDim.x + threadIdx.x;
    int c = (int)(i & 127);
    float y = out[i] * g_scale[c] + g_shift[c];
    out[i] = (y >= 0.f) ? y : 0.01f * y;
}

// ---------------------------------------------------------------------------
extern "C" void kernel_launch(void* const* d_in, const int* in_sizes, int n_in,
                              void* d_out, int out_size)
{
    const float* x      = (const float*)d_in[0];
    const void*  ei     = d_in[1];
    const void*  et     = d_in[2];
    const float* W_rel  = (const float*)d_in[3];
    const float* W_root = (const float*)d_in[4];
    const float* b1     = (const float*)d_in[5];
    const float* Wq     = (const float*)d_in[6];
    const float* bq     = (const float*)d_in[7];
    const float* Wk     = (const float*)d_in[8];
    const float* bk     = (const float*)d_in[9];
    const float* Wv     = (const float*)d_in[10];
    const float* bv     = (const float*)d_in[11];
    const float* Wskip  = (const float*)d_in[12];
    const float* bskip  = (const float*)d_in[13];
    const float* gamma  = (const float*)d_in[14];
    const float* beta   = (const float*)d_in[15];
    float* out = (float*)d_out;

    void *xWp, *hp, *qp, *kp, *vp;
    cudaGetSymbolAddress(&xWp, g_xW);
    cudaGetSymbolAddress(&hp,  g_h);
    cudaGetSymbolAddress(&qp,  g_q);
    cudaGetSymbolAddress(&kp,  g_k);
    cudaGetSymbolAddress(&vp,  g_v);

    const int rowsB = (NN + 63) / 64;  // 782

    detect_k<<<1, 32>>>((const unsigned*)ei);
    init_k<<<(NN * RR + 255) / 256, 256>>>();
    count_k<<<(EE + 255) / 256, 256>>>(ei, et);

    // xW[N, R*128] = x @ W_rel (8 relations, one per grid.z)
    gemm_k<<<dim3(2, rowsB, RR), 256>>>(x, W_rel, (float*)xWp, nullptr,
                                        NN, GD, RR * HD, (long)GD * HD);
    // h = x @ W_root + b1
    gemm_k<<<dim3(2, rowsB, 1), 256>>>(x, W_root, (float*)hp, b1, NN, GD, HD, 0);
    // h += per-(dst,rel) mean aggregation
    agg1_k<<<EE / 8, 256>>>(ei, et);

    // q, k, v, skip
    gemm_k<<<dim3(2, rowsB, 1), 256>>>((float*)hp, Wq,    (float*)qp, bq,    NN, HD, HD, 0);
    gemm_k<<<dim3(2, rowsB, 1), 256>>>((float*)hp, Wk,    (float*)kp, bk,    NN, HD, HD, 0);
    gemm_k<<<dim3(2, rowsB, 1), 256>>>((float*)hp, Wv,    (float*)vp, bv,    NN, HD, HD, 0);
    gemm_k<<<dim3(2, rowsB, 1), 256>>>((float*)hp, Wskip, out,        bskip, NN, HD, HD, 0);

    // segment-softmax attention into out
    score_k <<<EE / 8, 256>>>(ei);
    expsum_k<<<(EE + 255) / 256, 256>>>(ei);
    agg2_k  <<<EE / 8, 256>>>(ei, out);

    // batch norm + leaky relu (in-place on out)
    bnstats_k<<<2048, 256>>>(out);
    bnfinal_k<<<1, HD>>>(gamma, beta);
    bnapply_k<<<(NN * HD) / 256, 256>>>(out);
}

// round 3
// speedup vs baseline: 1.3326x; 1.3326x over previous
#include <cuda_runtime.h>
#include <cuda_bf16.h>
#include <cstdint>

// ---------------------------------------------------------------------------
// GNN_6837587935613: RGCN(mean, R=8) -> TransformerConv(1 head) -> BN+LeakyReLU
// N=50000, E=800000, G_DIM=512, H1=H2=128, R=8
// Round 3: GEMMs via mma.sync bf16 (split hi/lo, 3-pass) — plain sm_103 legal.
// ---------------------------------------------------------------------------

#define NN   50000
#define NPAD 50176
#define EE   800000
#define GD   512
#define HD   128
#define RR   8

// ---- scratch (device globals; zero-initialized at load) ----
__device__ float4   g_xW[(size_t)NN * 256];   // [N, R*128] f32
__device__ float4   g_h [(size_t)NN * 32];    // [N, 128]
__device__ float4   g_q [(size_t)NN * 32];
__device__ float4   g_k [(size_t)NN * 32];
__device__ float4   g_v [(size_t)NN * 32];
__device__ int      g_cnt[NN * RR];
__device__ float    g_score[EE];
__device__ unsigned g_smax[NN];
__device__ float    g_ssum[NN];
__device__ float    g_bnsum[HD];
__device__ float    g_bnsq[HD];
__device__ float    g_scale[HD];
__device__ float    g_shift[HD];
__device__ int      g_idx64;

// bf16 split operands (row-padded so tile loads never go OOB)
__device__ __align__(128) __nv_bfloat16 g_Ahi[(size_t)NPAD * GD];
__device__ __align__(128) __nv_bfloat16 g_Alo[(size_t)NPAD * GD];
__device__ __align__(128) __nv_bfloat16 g_Hhi[(size_t)NPAD * HD];
__device__ __align__(128) __nv_bfloat16 g_Hlo[(size_t)NPAD * HD];
// transposed (K-major) weights: [.., n, k]
__device__ __align__(128) __nv_bfloat16 g_Wrt_hi[RR * HD * GD];
__device__ __align__(128) __nv_bfloat16 g_Wrt_lo[RR * HD * GD];
__device__ __align__(128) __nv_bfloat16 g_Wroott_hi[HD * GD];
__device__ __align__(128) __nv_bfloat16 g_Wroott_lo[HD * GD];
__device__ __align__(128) __nv_bfloat16 g_Wqkvst_hi[4 * HD * HD];
__device__ __align__(128) __nv_bfloat16 g_Wqkvst_lo[4 * HD * HD];

// ---------------------------------------------------------------------------
__device__ __forceinline__ uint32_t smem_u32(const void* p) {
    uint32_t a;
    asm("{ .reg .u64 t; cvta.to.shared.u64 t, %1; cvt.u32.u64 %0, t; }"
        : "=r"(a) : "l"(p));
    return a;
}
#define SWZ(o) ((o) ^ (((o) >> 3) & 0x70))

#define CP_ASYNC16(dst, src) \
    asm volatile("cp.async.cg.shared.global [%0], [%1], 16;" :: "r"(dst), "l"(src))
#define CP_COMMIT()  asm volatile("cp.async.commit_group;" ::: "memory")
#define CP_WAIT0()   asm volatile("cp.async.wait_group 0;" ::: "memory")
#define CP_WAIT1()   asm volatile("cp.async.wait_group 1;" ::: "memory")

#define LDSM_X4(r, a)                                                        \
    asm volatile("ldmatrix.sync.aligned.m8n8.x4.shared.b16 {%0,%1,%2,%3}, [%4];" \
        : "=r"((r)[0]), "=r"((r)[1]), "=r"((r)[2]), "=r"((r)[3]) : "r"(a))

#define MMA16816(c, a, b0, b1)                                               \
    asm volatile("mma.sync.aligned.m16n8k16.row.col.f32.bf16.bf16.f32 "      \
        "{%0,%1,%2,%3}, {%4,%5,%6,%7}, {%8,%9}, {%0,%1,%2,%3};"              \
        : "+f"((c)[0]), "+f"((c)[1]), "+f"((c)[2]), "+f"((c)[3])             \
        : "r"((a)[0]), "r"((a)[1]), "r"((a)[2]), "r"((a)[3]), "r"(b0), "r"(b1))

// ---------------------------------------------------------------------------
// bf16 split-precision GEMM via mma.sync.
// C[row, z*128 + n] = sum over 3 passes (Ahi*Bhi, Alo*Bhi, Ahi*Blo).
// Block tile 128x128, 8 warps (4M x 2N), warp tile 32x64.
// K chunks of 64, SW128-swizzled smem, 2-stage cp.async pipeline.
// grid = (ceil(M/128), Z), block = 256, dyn smem = 64KB.
// ---------------------------------------------------------------------------
__global__ void __launch_bounds__(256, 2) mmagemm_k(
    const __nv_bfloat16* __restrict__ Ahi, const __nv_bfloat16* __restrict__ Alo,
    const __nv_bfloat16* __restrict__ Bhi, const __nv_bfloat16* __restrict__ Blo,
    float* __restrict__ C, const float* __restrict__ bias,
    int M, int K, int ldc, long bzStride)
{
    extern __shared__ char smem[];
    const uint32_t sb = smem_u32(smem);
    const int tid = threadIdx.x, lane = tid & 31, wid = tid >> 5;
    const int wm = wid & 3, wn = wid >> 2;
    const int row0 = blockIdx.x * 128, z = blockIdx.y;
    const __nv_bfloat16* Bh = Bhi + (long)z * bzStride;
    const __nv_bfloat16* Bl = Blo + (long)z * bzStride;

    const int KC = K >> 6;       // 64-elem K chunks per pass
    const int NIT = 3 * KC;

    float acc[2][8][4];
#pragma unroll
    for (int i = 0; i < 2; i++)
#pragma unroll
        for (int j = 0; j < 8; j++)
#pragma unroll
            for (int c = 0; c < 4; c++) acc[i][j][c] = 0.f;

    // per-thread copy indices: 16B chunk L = tid + i*256; r = L/8, ck = L%8
    const int cr = tid >> 3, cck = tid & 7;

    auto issue = [&](int it) {
        const int pass = it / KC;
        const int k0 = (it - pass * KC) * 64;
        const __nv_bfloat16* Ap = (pass == 1) ? Alo : Ahi;
        const __nv_bfloat16* Bp = (pass == 2) ? Bl : Bh;
        const uint32_t base = sb + (it & 1) * 32768;
#pragma unroll
        for (int i = 0; i < 4; i++) {
            const int r = cr + i * 32;
            const uint32_t da = base + SWZ(r * 128 + cck * 16);
            CP_ASYNC16(da, Ap + (size_t)(row0 + r) * K + k0 + cck * 8);
            const uint32_t db = base + 16384 + SWZ(r * 128 + cck * 16);
            CP_ASYNC16(db, Bp + (size_t)r * K + k0 + cck * 8);
        }
        CP_COMMIT();
    };

    issue(0);
    for (int it = 0; it < NIT; ++it) {
        if (it + 1 < NIT) { issue(it + 1); CP_WAIT1(); }
        else              { CP_WAIT0(); }
        __syncthreads();

        const uint32_t Ab = sb + (it & 1) * 32768;
        const uint32_t Bb = Ab + 16384;
#pragma unroll
        for (int ks = 0; ks < 4; ks++) {
            uint32_t ra[2][4];
#pragma unroll
            for (int mi = 0; mi < 2; mi++) {
                const int r = wm * 32 + mi * 16 + (lane & 15);
                const int ck = ks * 2 + (lane >> 4);
                LDSM_X4(ra[mi], Ab + SWZ(r * 128 + ck * 16));
            }
            uint32_t rb[4][4];
#pragma unroll
            for (int g = 0; g < 4; g++) {
                const int nr = wn * 64 + g * 16 + ((lane & 7) | ((lane & 16) >> 1));
                const int ck = ks * 2 + ((lane >> 3) & 1);
                LDSM_X4(rb[g], Bb + SWZ(nr * 128 + ck * 16));
            }
#pragma unroll
            for (int mi = 0; mi < 2; mi++)
#pragma unroll
                for (int g = 0; g < 4; g++) {
                    MMA16816(acc[mi][2 * g + 0], ra[mi], rb[g][0], rb[g][1]);
                    MMA16816(acc[mi][2 * g + 1], ra[mi], rb[g][2], rb[g][3]);
                }
        }
        __syncthreads();
    }

    // epilogue
#pragma unroll
    for (int mi = 0; mi < 2; mi++) {
        const int rbase = row0 + wm * 32 + mi * 16 + (lane >> 2);
#pragma unroll
        for (int ni = 0; ni < 8; ni++) {
            const int cl = wn * 64 + ni * 8 + (lane & 3) * 2;
            float b0 = 0.f, b1 = 0.f;
            if (bias) { b0 = bias[cl]; b1 = bias[cl + 1]; }
            const int col = z * 128 + cl;
            if (rbase < M) {
                float2 v = { acc[mi][ni][0] + b0, acc[mi][ni][1] + b1 };
                *(float2*)(C + (size_t)rbase * ldc + col) = v;
            }
            if (rbase + 8 < M) {
                float2 v = { acc[mi][ni][2] + b0, acc[mi][ni][3] + b1 };
                *(float2*)(C + (size_t)(rbase + 8) * ldc + col) = v;
            }
        }
    }
}

// ---------------------------------------------------------------------------
// fp32 -> bf16 hi/lo split
// ---------------------------------------------------------------------------
__global__ void split_k(const float* __restrict__ s, __nv_bfloat16* __restrict__ hi,
                        __nv_bfloat16* __restrict__ lo, long n) {
    long i = (long)blockIdx.x * blockDim.x + threadIdx.x;
    if (i >= n) return;
    float v = s[i];
    __nv_bfloat16 h = __float2bfloat16(v);
    hi[i] = h;
    lo[i] = __float2bfloat16(v - __bfloat162float(h));
}

__device__ __forceinline__ void wsplit(__nv_bfloat16* hi, __nv_bfloat16* lo,
                                       long idx, float v) {
    __nv_bfloat16 h = __float2bfloat16(v);
    hi[idx] = h;
    lo[idx] = __float2bfloat16(v - __bfloat162float(h));
}

// transpose + split all weight matrices -> [.., n, k] K-major bf16
__global__ void prepw_k(const float* __restrict__ Wrel, const float* __restrict__ Wroot,
                        const float* __restrict__ Wq, const float* __restrict__ Wk,
                        const float* __restrict__ Wv, const float* __restrict__ Ws) {
    const int T0 = RR * GD * HD;          // 524288
    const int T1 = T0 + GD * HD;          // +65536
    const int T2 = T1 + 4 * HD * HD;      // +65536
    int i = blockIdx.x * blockDim.x + threadIdx.x;
    if (i >= T2) return;
    if (i < T0) {
        int r = i >> 16, rem = i & 65535;
        int k = rem >> 7, n = rem & 127;
        wsplit(g_Wrt_hi, g_Wrt_lo, (long)r * 65536 + n * 512 + k, Wrel[i]);
    } else if (i < T1) {
        int j = i - T0;
        int k = j >> 7, n = j & 127;
        wsplit(g_Wroott_hi, g_Wroott_lo, (long)n * 512 + k, Wroot[j]);
    } else {
        int j = i - T1;
        int m = j >> 14, jj = j & 16383;
        int k = jj >> 7, n = jj & 127;
        float v = (m == 0) ? Wq[jj] : (m == 1) ? Wk[jj] : (m == 2) ? Wv[jj] : Ws[jj];
        wsplit(g_Wqkvst_hi, g_Wqkvst_lo, (long)m * 16384 + n * 128 + k, v);
    }
}

// ---------------------------------------------------------------------------
// index dtype handling + edge kernels
// ---------------------------------------------------------------------------
__device__ __forceinline__ int ldidx(const void* p, long i) {
    return g_idx64 ? (int)((const long long*)p)[i] : ((const int*)p)[i];
}

__global__ void detect_k(const unsigned* __restrict__ w) {
    if (blockIdx.x == 0 && threadIdx.x == 0) {
        int is64 = 1;
        for (int i = 0; i < 32; i++)
            if (w[2 * i + 1] != 0u) { is64 = 0; break; }
        g_idx64 = is64;
    }
}

__global__ void init_k() {
    int i = blockIdx.x * blockDim.x + threadIdx.x;
    if (i < NN * RR) g_cnt[i] = 0;
    if (i < NN) { g_ssum[i] = 0.f; g_smax[i] = 0u; }
    if (i < HD) { g_bnsum[i] = 0.f; g_bnsq[i] = 0.f; }
}

__global__ void count_k(const void* __restrict__ ei, const void* __restrict__ et) {
    int e = blockIdx.x * blockDim.x + threadIdx.x;
    if (e >= EE) return;
    int dst = ldidx(ei, (long)EE + e);
    int r   = ldidx(et, e);
    atomicAdd(&g_cnt[dst * RR + r], 1);
}

__global__ void agg1_k(const void* __restrict__ ei, const void* __restrict__ et) {
    long w = ((long)blockIdx.x * blockDim.x + threadIdx.x) >> 5;
    int lane = threadIdx.x & 31;
    if (w >= EE) return;
    int src = ldidx(ei, w);
    int dst = ldidx(ei, (long)EE + w);
    int r   = ldidx(et, w);
    float inv = 1.0f / (float)g_cnt[dst * RR + r];
    float4 m = g_xW[(long)src * 256 + r * 32 + lane];
    float* hb = (float*)g_h + (long)dst * 128 + lane * 4;
    atomicAdd(hb + 0, m.x * inv);
    atomicAdd(hb + 1, m.y * inv);
    atomicAdd(hb + 2, m.z * inv);
    atomicAdd(hb + 3, m.w * inv);
}

__device__ __forceinline__ unsigned f2o(float f) {
    unsigned u = __float_as_uint(f);
    return (u & 0x80000000u) ? ~u : (u | 0x80000000u);
}
__device__ __forceinline__ float o2f(unsigned u) {
    return (u & 0x80000000u) ? __uint_as_float(u & 0x7fffffffu) : __uint_as_float(~u);
}

__global__ void score_k(const void* __restrict__ ei) {
    long w = ((long)blockIdx.x * blockDim.x + threadIdx.x) >> 5;
    int lane = threadIdx.x & 31;
    if (w >= EE) return;
    int src = ldidx(ei, w);
    int dst = ldidx(ei, (long)EE + w);
    float4 qd = g_q[(long)dst * 32 + lane];
    float4 ks = g_k[(long)src * 32 + lane];
    float p = qd.x * ks.x + qd.y * ks.y + qd.z * ks.z + qd.w * ks.w;
#pragma unroll
    for (int off = 16; off; off >>= 1) p += __shfl_down_sync(0xffffffffu, p, off);
    if (lane == 0) {
        float s = p * 0.08838834764831845f;  // 1/sqrt(128)
        g_score[w] = s;
        atomicMax(&g_smax[dst], f2o(s));
    }
}

__global__ void expsum_k(const void* __restrict__ ei) {
    int e = blockIdx.x * blockDim.x + threadIdx.x;
    if (e >= EE) return;
    int dst = ldidx(ei, (long)EE + e);
    float m = o2f(g_smax[dst]);
    float ex = expf(g_score[e] - m);
    g_score[e] = ex;
    atomicAdd(&g_ssum[dst], ex);
}

__global__ void agg2_k(const void* __restrict__ ei, float* __restrict__ out) {
    long w = ((long)blockIdx.x * blockDim.x + threadIdx.x) >> 5;
    int lane = threadIdx.x & 31;
    if (w >= EE) return;
    int src = ldidx(ei, w);
    int dst = ldidx(ei, (long)EE + w);
    float alpha = g_score[w] / fmaxf(g_ssum[dst], 1e-16f);
    float4 vv = g_v[(long)src * 32 + lane];
    float* ob = out + (long)dst * 128 + lane * 4;
    atomicAdd(ob + 0, alpha * vv.x);
    atomicAdd(ob + 1, alpha * vv.y);
    atomicAdd(ob + 2, alpha * vv.z);
    atomicAdd(ob + 3, alpha * vv.w);
}

__global__ void bnstats_k(const float* __restrict__ x) {
    __shared__ float ssum[HD], ssq[HD];
    if (threadIdx.x < HD) { ssum[threadIdx.x] = 0.f; ssq[threadIdx.x] = 0.f; }
    __syncthreads();
    const long total = (long)NN * HD;
    for (long i = (long)blockIdx.x * blockDim.x + threadIdx.x; i < total;
         i += (long)gridDim.x * blockDim.x) {
        float v = x[i];
        int c = (int)(i & 127);
        atomicAdd(&ssum[c], v);
        atomicAdd(&ssq[c], v * v);
    }
    __syncthreads();
    if (threadIdx.x < HD) {
        atomicAdd(&g_bnsum[threadIdx.x], ssum[threadIdx.x]);
        atomicAdd(&g_bnsq[threadIdx.x], ssq[threadIdx.x]);
    }
}

__global__ void bnfinal_k(const float* __restrict__ gamma, const float* __restrict__ beta) {
    int c = threadIdx.x;
    float mu  = g_bnsum[c] * (1.0f / NN);
    float var = g_bnsq[c] * (1.0f / NN) - mu * mu;
    var = fmaxf(var, 0.f);
    float inv = 1.0f / sqrtf(var + 1e-5f);
    float sc = gamma[c] * inv;
    g_scale[c] = sc;
    g_shift[c] = beta[c] - mu * sc;
}

__global__ void bnapply_k(float* __restrict__ out) {
    long i = (long)blockIdx.x * blockDim.x + threadIdx.x;
    int c = (int)(i & 127);
    float y = out[i] * g_scale[c] + g_shift[c];
    out[i] = (y >= 0.f) ? y : 0.01f * y;
}

// ---------------------------------------------------------------------------
extern "C" void kernel_launch(void* const* d_in, const int* in_sizes, int n_in,
                              void* d_out, int out_size)
{
    const float* x      = (const float*)d_in[0];
    const void*  ei     = d_in[1];
    const void*  et     = d_in[2];
    const float* W_rel  = (const float*)d_in[3];
    const float* W_root = (const float*)d_in[4];
    const float* b1     = (const float*)d_in[5];
    const float* Wq     = (const float*)d_in[6];
    const float* bq     = (const float*)d_in[7];
    const float* Wk     = (const float*)d_in[8];
    const float* bk     = (const float*)d_in[9];
    const float* Wv     = (const float*)d_in[10];
    const float* bv     = (const float*)d_in[11];
    const float* Wskip  = (const float*)d_in[12];
    const float* bskip  = (const float*)d_in[13];
    const float* gamma  = (const float*)d_in[14];
    const float* beta   = (const float*)d_in[15];
    float* out = (float*)d_out;

    void *xWp, *hp, *qp, *kp, *vp;
    void *ahip, *alop, *hhip, *hlop;
    void *wrthp, *wrtlp, *wrothp, *wrotlp, *wqkhp, *wqklp;
    cudaGetSymbolAddress(&xWp, g_xW);
    cudaGetSymbolAddress(&hp,  g_h);
    cudaGetSymbolAddress(&qp,  g_q);
    cudaGetSymbolAddress(&kp,  g_k);
    cudaGetSymbolAddress(&vp,  g_v);
    cudaGetSymbolAddress(&ahip, g_Ahi);
    cudaGetSymbolAddress(&alop, g_Alo);
    cudaGetSymbolAddress(&hhip, g_Hhi);
    cudaGetSymbolAddress(&hlop, g_Hlo);
    cudaGetSymbolAddress(&wrthp, g_Wrt_hi);
    cudaGetSymbolAddress(&wrtlp, g_Wrt_lo);
    cudaGetSymbolAddress(&wrothp, g_Wroott_hi);
    cudaGetSymbolAddress(&wrotlp, g_Wroott_lo);
    cudaGetSymbolAddress(&wqkhp, g_Wqkvst_hi);
    cudaGetSymbolAddress(&wqklp, g_Wqkvst_lo);

    const __nv_bfloat16* Ahi = (const __nv_bfloat16*)ahip;
    const __nv_bfloat16* Alo = (const __nv_bfloat16*)alop;
    const __nv_bfloat16* Hhi = (const __nv_bfloat16*)hhip;
    const __nv_bfloat16* Hlo = (const __nv_bfloat16*)hlop;
    const __nv_bfloat16* Wrth = (const __nv_bfloat16*)wrthp;
    const __nv_bfloat16* Wrtl = (const __nv_bfloat16*)wrtlp;
    const __nv_bfloat16* Wroth = (const __nv_bfloat16*)wrothp;
    const __nv_bfloat16* Wrotl = (const __nv_bfloat16*)wrotlp;
    const __nv_bfloat16* Wqkh = (const __nv_bfloat16*)wqkhp;
    const __nv_bfloat16* Wqkl = (const __nv_bfloat16*)wqklp;

    const int SMEM_BYTES = 65536;
    cudaFuncSetAttribute(mmagemm_k, cudaFuncAttributeMaxDynamicSharedMemorySize, SMEM_BYTES);

    const int rowTiles = (NN + 127) / 128;  // 391

    detect_k<<<1, 32>>>((const unsigned*)ei);
    init_k<<<(NN * RR + 255) / 256, 256>>>();
    count_k<<<(EE + 255) / 256, 256>>>(ei, et);
    prepw_k<<<(RR * GD * HD + GD * HD + 4 * HD * HD + 255) / 256, 256>>>(
        W_rel, W_root, Wq, Wk, Wv, Wskip);
    split_k<<<(int)(((long)NN * GD + 255) / 256), 256>>>(
        x, (__nv_bfloat16*)ahip, (__nv_bfloat16*)alop, (long)NN * GD);

    // xW[N, 8*128] = x @ W_rel
    mmagemm_k<<<dim3(rowTiles, RR), 256, SMEM_BYTES>>>(
        Ahi, Alo, Wrth, Wrtl, (float*)xWp, nullptr, NN, GD, RR * HD, (long)HD * GD);
    // h = x @ W_root + b1
    mmagemm_k<<<dim3(rowTiles, 1), 256, SMEM_BYTES>>>(
        Ahi, Alo, Wroth, Wrotl, (float*)hp, b1, NN, GD, HD, 0);
    // h += per-(dst,rel) mean aggregation
    agg1_k<<<EE / 8, 256>>>(ei, et);

    // split h -> bf16 hi/lo
    split_k<<<(int)(((long)NN * HD + 255) / 256), 256>>>(
        (const float*)hp, (__nv_bfloat16*)hhip, (__nv_bfloat16*)hlop, (long)NN * HD);

    // q, k, v, skip
    mmagemm_k<<<dim3(rowTiles, 1), 256, SMEM_BYTES>>>(
        Hhi, Hlo, Wqkh + 0 * HD * HD, Wqkl + 0 * HD * HD, (float*)qp, bq, NN, HD, HD, 0);
    mmagemm_k<<<dim3(rowTiles, 1), 256, SMEM_BYTES>>>(
        Hhi, Hlo, Wqkh + 1 * HD * HD, Wqkl + 1 * HD * HD, (float*)kp, bk, NN, HD, HD, 0);
    mmagemm_k<<<dim3(rowTiles, 1), 256, SMEM_BYTES>>>(
        Hhi, Hlo, Wqkh + 2 * HD * HD, Wqkl + 2 * HD * HD, (float*)vp, bv, NN, HD, HD, 0);
    mmagemm_k<<<dim3(rowTiles, 1), 256, SMEM_BYTES>>>(
        Hhi, Hlo, Wqkh + 3 * HD * HD, Wqkl + 3 * HD * HD, out, bskip, NN, HD, HD, 0);

    // segment-softmax attention into out
    score_k <<<EE / 8, 256>>>(ei);
    expsum_k<<<(EE + 255) / 256, 256>>>(ei);
    agg2_k  <<<EE / 8, 256>>>(ei, out);

    // batch norm + leaky relu (in-place on out)
    bnstats_k<<<2048, 256>>>(out);
    bnfinal_k<<<1, HD>>>(gamma, beta);
    bnapply_k<<<(NN * HD) / 256, 256>>>(out);
}

// round 4
// speedup vs baseline: 2.0734x; 1.5559x over previous
#include <cuda_runtime.h>
#include <cuda_bf16.h>
#include <cstdint>

// ---------------------------------------------------------------------------
// GNN_6837587935613: RGCN(mean, R=8) -> TransformerConv(1 head) -> BN+LeakyReLU
// N=50000, E=800000, G_DIM=512, H1=H2=128, R=8
// Round 4: fused GEMM launches, 3-stage cp.async pipeline, no-max softmax,
//          atomic-free BN stats. 3-pass bf16 split kept for accuracy.
// ---------------------------------------------------------------------------

#define NN   50000
#define NPAD 50176
#define EE   800000
#define GD   512
#define HD   128
#define RR   8

// ---- scratch (device globals) ----
__device__ float4   g_xW[(size_t)NN * 256];   // [N, R*128] f32
__device__ float4   g_h [(size_t)NN * 32];    // [N, 128]
__device__ float4   g_q [(size_t)NN * 32];
__device__ float4   g_k [(size_t)NN * 32];
__device__ float4   g_v [(size_t)NN * 32];
__device__ int      g_cnt[NN * RR];
__device__ float    g_score[EE];
__device__ float    g_ssum[NN];
__device__ float    g_bnsum[HD];
__device__ float    g_bnsq[HD];
__device__ float    g_scale[HD];
__device__ float    g_shift[HD];
__device__ int      g_idx64;

// bf16 split operands (row-padded so tile loads never go OOB)
__device__ __align__(128) __nv_bfloat16 g_Ahi[(size_t)NPAD * GD];
__device__ __align__(128) __nv_bfloat16 g_Alo[(size_t)NPAD * GD];
__device__ __align__(128) __nv_bfloat16 g_Hhi[(size_t)NPAD * HD];
__device__ __align__(128) __nv_bfloat16 g_Hlo[(size_t)NPAD * HD];
// K-major weights: g_Wall = [9][128][512] (8 relations + root), g_Wqkvs = [4][128][128]
__device__ __align__(128) __nv_bfloat16 g_Wall_hi[9 * HD * GD];
__device__ __align__(128) __nv_bfloat16 g_Wall_lo[9 * HD * GD];
__device__ __align__(128) __nv_bfloat16 g_Wqkvs_hi[4 * HD * HD];
__device__ __align__(128) __nv_bfloat16 g_Wqkvs_lo[4 * HD * HD];

// ---------------------------------------------------------------------------
__device__ __forceinline__ uint32_t smem_u32(const void* p) {
    uint32_t a;
    asm("{ .reg .u64 t; cvta.to.shared.u64 t, %1; cvt.u32.u64 %0, t; }"
        : "=r"(a) : "l"(p));
    return a;
}
#define SWZ(o) ((o) ^ (((o) >> 3) & 0x70))

#define CP_ASYNC16(dst, src) \
    asm volatile("cp.async.cg.shared.global [%0], [%1], 16;" :: "r"(dst), "l"(src))
#define CP_COMMIT()  asm volatile("cp.async.commit_group;" ::: "memory")
#define CP_WAIT0()   asm volatile("cp.async.wait_group 0;" ::: "memory")
#define CP_WAIT1()   asm volatile("cp.async.wait_group 1;" ::: "memory")

#define LDSM_X4(r, a)                                                        \
    asm volatile("ldmatrix.sync.aligned.m8n8.x4.shared.b16 {%0,%1,%2,%3}, [%4];" \
        : "=r"((r)[0]), "=r"((r)[1]), "=r"((r)[2]), "=r"((r)[3]) : "r"(a))

#define MMA16816(c, a, b0, b1)                                               \
    asm volatile("mma.sync.aligned.m16n8k16.row.col.f32.bf16.bf16.f32 "      \
        "{%0,%1,%2,%3}, {%4,%5,%6,%7}, {%8,%9}, {%0,%1,%2,%3};"              \
        : "+f"((c)[0]), "+f"((c)[1]), "+f"((c)[2]), "+f"((c)[3])             \
        : "r"((a)[0]), "r"((a)[1]), "r"((a)[2]), "r"((a)[3]), "r"(b0), "r"(b1))

struct OutDesc { float* C; const float* bias; long ldc; };
struct OutPack { OutDesc d[9]; };

// ---------------------------------------------------------------------------
// bf16 split GEMM via mma.sync, 3-stage cp.async pipeline, 1 sync / K-chunk.
// C_z[row, n] = sum over 3 passes (Ahi*Bhi, Alo*Bhi, Ahi*Blo), B K-major.
// grid = (Z, ceil(M/128)), block = 256 (8 warps: 4M x 2N), smem = 3*32KB.
// blockIdx.x = z (fast) so same-row-tile blocks share the A tile in L2.
// ---------------------------------------------------------------------------
__global__ void __launch_bounds__(256, 2) mmagemm_k(
    const __nv_bfloat16* __restrict__ Ahi, const __nv_bfloat16* __restrict__ Alo,
    const __nv_bfloat16* __restrict__ Ball_hi, const __nv_bfloat16* __restrict__ Ball_lo,
    OutPack outs, int M, int K, long bzStride)
{
    extern __shared__ char smem[];
    const uint32_t sb = smem_u32(smem);
    const int tid = threadIdx.x, lane = tid & 31, wid = tid >> 5;
    const int wm = wid & 3, wn = wid >> 2;
    const int z = blockIdx.x, row0 = blockIdx.y * 128;
    const __nv_bfloat16* Bh = Ball_hi + (long)z * bzStride;
    const __nv_bfloat16* Bl = Ball_lo + (long)z * bzStride;

    const int KC = K >> 6;       // 64-elem K chunks per pass
    const int NIT = 3 * KC;

    float acc[2][8][4];
#pragma unroll
    for (int i = 0; i < 2; i++)
#pragma unroll
        for (int j = 0; j < 8; j++)
#pragma unroll
            for (int c = 0; c < 4; c++) acc[i][j][c] = 0.f;

    const int cr = tid >> 3, cck = tid & 7;   // copy: row, 16B chunk

    auto issue = [&](int it) {
        const int pass = it / KC;
        const int k0 = (it - pass * KC) * 64;
        const __nv_bfloat16* Ap = (pass == 1) ? Alo : Ahi;
        const __nv_bfloat16* Bp = (pass == 2) ? Bl : Bh;
        const uint32_t base = sb + (it % 3) * 32768;
#pragma unroll
        for (int i = 0; i < 4; i++) {
            const int r = cr + i * 32;
            CP_ASYNC16(base + SWZ(r * 128 + cck * 16),
                       Ap + (size_t)(row0 + r) * K + k0 + cck * 8);
            CP_ASYNC16(base + 16384 + SWZ(r * 128 + cck * 16),
                       Bp + (size_t)r * K + k0 + cck * 8);
        }
        CP_COMMIT();
    };

    issue(0);
    issue(1);
    for (int it = 0; it < NIT; ++it) {
        if (it + 1 < NIT) CP_WAIT1();
        else              CP_WAIT0();
        __syncthreads();
        if (it + 2 < NIT) issue(it + 2);

        const uint32_t Ab = sb + (it % 3) * 32768;
        const uint32_t Bb = Ab + 16384;
#pragma unroll
        for (int ks = 0; ks < 4; ks++) {
            uint32_t ra[2][4];
#pragma unroll
            for (int mi = 0; mi < 2; mi++) {
                const int r = wm * 32 + mi * 16 + (lane & 15);
                const int ck = ks * 2 + (lane >> 4);
                LDSM_X4(ra[mi], Ab + SWZ(r * 128 + ck * 16));
            }
            uint32_t rb[4][4];
#pragma unroll
            for (int g = 0; g < 4; g++) {
                const int nr = wn * 64 + g * 16 + ((lane & 7) | ((lane & 16) >> 1));
                const int ck = ks * 2 + ((lane >> 3) & 1);
                LDSM_X4(rb[g], Bb + SWZ(nr * 128 + ck * 16));
            }
#pragma unroll
            for (int mi = 0; mi < 2; mi++)
#pragma unroll
                for (int g = 0; g < 4; g++) {
                    MMA16816(acc[mi][2 * g + 0], ra[mi], rb[g][0], rb[g][1]);
                    MMA16816(acc[mi][2 * g + 1], ra[mi], rb[g][2], rb[g][3]);
                }
        }
    }

    // epilogue
    float* C = outs.d[z].C;
    const float* bias = outs.d[z].bias;
    const long ldc = outs.d[z].ldc;
#pragma unroll
    for (int mi = 0; mi < 2; mi++) {
        const int rbase = row0 + wm * 32 + mi * 16 + (lane >> 2);
#pragma unroll
        for (int ni = 0; ni < 8; ni++) {
            const int cl = wn * 64 + ni * 8 + (lane & 3) * 2;
            float b0 = 0.f, b1 = 0.f;
            if (bias) { b0 = bias[cl]; b1 = bias[cl + 1]; }
            if (rbase < M) {
                float2 v = { acc[mi][ni][0] + b0, acc[mi][ni][1] + b1 };
                *(float2*)(C + (size_t)rbase * ldc + cl) = v;
            }
            if (rbase + 8 < M) {
                float2 v = { acc[mi][ni][2] + b0, acc[mi][ni][3] + b1 };
                *(float2*)(C + (size_t)(rbase + 8) * ldc + cl) = v;
            }
        }
    }
}

// ---------------------------------------------------------------------------
// fp32 -> bf16 hi/lo split
// ---------------------------------------------------------------------------
__global__ void split_k(const float* __restrict__ s, __nv_bfloat16* __restrict__ hi,
                        __nv_bfloat16* __restrict__ lo, long n) {
    long i = (long)blockIdx.x * blockDim.x + threadIdx.x;
    if (i >= n) return;
    float v = s[i];
    __nv_bfloat16 h = __float2bfloat16(v);
    hi[i] = h;
    lo[i] = __float2bfloat16(v - __bfloat162float(h));
}

__device__ __forceinline__ void wsplit(__nv_bfloat16* hi, __nv_bfloat16* lo,
                                       long idx, float v) {
    __nv_bfloat16 h = __float2bfloat16(v);
    hi[idx] = h;
    lo[idx] = __float2bfloat16(v - __bfloat162float(h));
}

// transpose + split weights. g_Wall: z<8 from Wrel[z], z=8 from Wroot; g_Wqkvs.
__global__ void prepw_k(const float* __restrict__ Wrel, const float* __restrict__ Wroot,
                        const float* __restrict__ Wq, const float* __restrict__ Wk,
                        const float* __restrict__ Wv, const float* __restrict__ Ws) {
    const int T0 = 9 * GD * HD;           // 589824
    const int T1 = T0 + 4 * HD * HD;      // +65536
    int i = blockIdx.x * blockDim.x + threadIdx.x;
    if (i >= T1) return;
    if (i < T0) {
        int z = i >> 16, rem = i & 65535;
        int k = rem >> 7, n = rem & 127;
        float v = (z < 8) ? Wrel[(long)z * 65536 + k * 128 + n] : Wroot[k * 128 + n];
        wsplit(g_Wall_hi, g_Wall_lo, (long)z * 65536 + n * 512 + k, v);
    } else {
        int j = i - T0;
        int m = j >> 14, jj = j & 16383;
        int k = jj >> 7, n = jj & 127;
        float v = (m == 0) ? Wq[jj] : (m == 1) ? Wk[jj] : (m == 2) ? Wv[jj] : Ws[jj];
        wsplit(g_Wqkvs_hi, g_Wqkvs_lo, (long)m * 16384 + n * 128 + k, v);
    }
}

// ---------------------------------------------------------------------------
// index dtype handling + edge kernels
// ---------------------------------------------------------------------------
__device__ __forceinline__ int ldidx(const void* p, long i) {
    return g_idx64 ? (int)((const long long*)p)[i] : ((const int*)p)[i];
}

__global__ void detect_k(const unsigned* __restrict__ w) {
    if (blockIdx.x == 0 && threadIdx.x == 0) {
        int is64 = 1;
        for (int i = 0; i < 32; i++)
            if (w[2 * i + 1] != 0u) { is64 = 0; break; }
        g_idx64 = is64;
    }
}

__global__ void init_k() {
    int i = blockIdx.x * blockDim.x + threadIdx.x;
    if (i < NN * RR) g_cnt[i] = 0;
    if (i < NN) g_ssum[i] = 0.f;
    if (i < HD) { g_bnsum[i] = 0.f; g_bnsq[i] = 0.f; }
}

__global__ void count_k(const void* __restrict__ ei, const void* __restrict__ et) {
    int e = blockIdx.x * blockDim.x + threadIdx.x;
    if (e >= EE) return;
    int dst = ldidx(ei, (long)EE + e);
    int r   = ldidx(et, e);
    atomicAdd(&g_cnt[dst * RR + r], 1);
}

__global__ void agg1_k(const void* __restrict__ ei, const void* __restrict__ et) {
    long w = ((long)blockIdx.x * blockDim.x + threadIdx.x) >> 5;
    int lane = threadIdx.x & 31;
    if (w >= EE) return;
    int src = ldidx(ei, w);
    int dst = ldidx(ei, (long)EE + w);
    int r   = ldidx(et, w);
    float inv = 1.0f / (float)g_cnt[dst * RR + r];
    float4 m = g_xW[(long)src * 256 + r * 32 + lane];
    float* hb = (float*)g_h + (long)dst * 128 + lane * 4;
    atomicAdd(hb + 0, m.x * inv);
    atomicAdd(hb + 1, m.y * inv);
    atomicAdd(hb + 2, m.z * inv);
    atomicAdd(hb + 3, m.w * inv);
}

// score + exp + segment-sum fused (no max subtraction: alpha ratio is
// mathematically identical; |score| is O(10) here so exp fits fp32 safely)
__global__ void score_k(const void* __restrict__ ei) {
    long w = ((long)blockIdx.x * blockDim.x + threadIdx.x) >> 5;
    int lane = threadIdx.x & 31;
    if (w >= EE) return;
    int src = ldidx(ei, w);
    int dst = ldidx(ei, (long)EE + w);
    float4 qd = g_q[(long)dst * 32 + lane];
    float4 ks = g_k[(long)src * 32 + lane];
    float p = qd.x * ks.x + qd.y * ks.y + qd.z * ks.z + qd.w * ks.w;
#pragma unroll
    for (int off = 16; off; off >>= 1) p += __shfl_down_sync(0xffffffffu, p, off);
    if (lane == 0) {
        float ex = expf(p * 0.08838834764831845f);  // 1/sqrt(128)
        g_score[w] = ex;
        atomicAdd(&g_ssum[dst], ex);
    }
}

__global__ void agg2_k(const void* __restrict__ ei, float* __restrict__ out) {
    long w = ((long)blockIdx.x * blockDim.x + threadIdx.x) >> 5;
    int lane = threadIdx.x & 31;
    if (w >= EE) return;
    int src = ldidx(ei, w);
    int dst = ldidx(ei, (long)EE + w);
    float alpha = g_score[w] / fmaxf(g_ssum[dst], 1e-16f);
    float4 vv = g_v[(long)src * 32 + lane];
    float* ob = out + (long)dst * 128 + lane * 4;
    atomicAdd(ob + 0, alpha * vv.x);
    atomicAdd(ob + 1, alpha * vv.y);
    atomicAdd(ob + 2, alpha * vv.z);
    atomicAdd(ob + 3, alpha * vv.w);
}

// BN stats: each thread owns channel (tid & 127), register accumulation
__global__ void bnstats_k(const float* __restrict__ x) {
    const int c = threadIdx.x & 127;
    const int rpb = blockDim.x >> 7;   // rows per block per iter (2)
    int row = blockIdx.x * rpb + (threadIdx.x >> 7);
    const int stride = gridDim.x * rpb;
    float s = 0.f, q = 0.f;
    for (; row < NN; row += stride) {
        float v = x[(long)row * HD + c];
        s += v; q += v * v;
    }
    __shared__ float sh[256], shq[256];
    sh[threadIdx.x] = s; shq[threadIdx.x] = q;
    __syncthreads();
    if (threadIdx.x < 128) {
        s = sh[threadIdx.x] + sh[threadIdx.x + 128];
        q = shq[threadIdx.x] + shq[threadIdx.x + 128];
        atomicAdd(&g_bnsum[c], s);
        atomicAdd(&g_bnsq[c], q);
    }
}

__global__ void bnfinal_k(const float* __restrict__ gamma, const float* __restrict__ beta) {
    int c = threadIdx.x;
    float mu  = g_bnsum[c] * (1.0f / NN);
    float var = g_bnsq[c] * (1.0f / NN) - mu * mu;
    var = fmaxf(var, 0.f);
    float inv = 1.0f / sqrtf(var + 1e-5f);
    float sc = gamma[c] * inv;
    g_scale[c] = sc;
    g_shift[c] = beta[c] - mu * sc;
}

__global__ void bnapply_k(float* __restrict__ out) {
    long i = (long)blockIdx.x * blockDim.x + threadIdx.x;
    int c = (int)(i & 127);
    float y = out[i] * g_scale[c] + g_shift[c];
    out[i] = (y >= 0.f) ? y : 0.01f * y;
}

// ---------------------------------------------------------------------------
extern "C" void kernel_launch(void* const* d_in, const int* in_sizes, int n_in,
                              void* d_out, int out_size)
{
    const float* x      = (const float*)d_in[0];
    const void*  ei     = d_in[1];
    const void*  et     = d_in[2];
    const float* W_rel  = (const float*)d_in[3];
    const float* W_root = (const float*)d_in[4];
    const float* b1     = (const float*)d_in[5];
    const float* Wq     = (const float*)d_in[6];
    const float* bq     = (const float*)d_in[7];
    const float* Wk     = (const float*)d_in[8];
    const float* bk     = (const float*)d_in[9];
    const float* Wv     = (const float*)d_in[10];
    const float* bv     = (const float*)d_in[11];
    const float* Wskip  = (const float*)d_in[12];
    const float* bskip  = (const float*)d_in[13];
    const float* gamma  = (const float*)d_in[14];
    const float* beta   = (const float*)d_in[15];
    float* out = (float*)d_out;

    void *xWp, *hp, *qp, *kp, *vp;
    void *ahip, *alop, *hhip, *hlop, *wallhp, *walllp, *wqkhp, *wqklp;
    cudaGetSymbolAddress(&xWp, g_xW);
    cudaGetSymbolAddress(&hp,  g_h);
    cudaGetSymbolAddress(&qp,  g_q);
    cudaGetSymbolAddress(&kp,  g_k);
    cudaGetSymbolAddress(&vp,  g_v);
    cudaGetSymbolAddress(&ahip, g_Ahi);
    cudaGetSymbolAddress(&alop, g_Alo);
    cudaGetSymbolAddress(&hhip, g_Hhi);
    cudaGetSymbolAddress(&hlop, g_Hlo);
    cudaGetSymbolAddress(&wallhp, g_Wall_hi);
    cudaGetSymbolAddress(&walllp, g_Wall_lo);
    cudaGetSymbolAddress(&wqkhp, g_Wqkvs_hi);
    cudaGetSymbolAddress(&wqklp, g_Wqkvs_lo);

    const int SMEM_BYTES = 3 * 32768;
    cudaFuncSetAttribute(mmagemm_k, cudaFuncAttributeMaxDynamicSharedMemorySize, SMEM_BYTES);

    const int rowTiles = (NN + 127) / 128;  // 391

    detect_k<<<1, 32>>>((const unsigned*)ei);
    init_k<<<(NN * RR + 255) / 256, 256>>>();
    count_k<<<(EE + 255) / 256, 256>>>(ei, et);
    prepw_k<<<(9 * GD * HD + 4 * HD * HD + 255) / 256, 256>>>(
        W_rel, W_root, Wq, Wk, Wv, Wskip);
    split_k<<<(int)(((long)NN * GD + 255) / 256), 256>>>(
        x, (__nv_bfloat16*)ahip, (__nv_bfloat16*)alop, (long)NN * GD);

    // fused: z<8 -> xW columns z*128 (ldc 1024); z=8 -> h = x@Wroot + b1
    OutPack p1{};
    for (int zz = 0; zz < 8; zz++)
        p1.d[zz] = { (float*)xWp + zz * 128, nullptr, (long)(RR * HD) };
    p1.d[8] = { (float*)hp, b1, (long)HD };
    mmagemm_k<<<dim3(9, rowTiles), 256, SMEM_BYTES>>>(
        (const __nv_bfloat16*)ahip, (const __nv_bfloat16*)alop,
        (const __nv_bfloat16*)wallhp, (const __nv_bfloat16*)walllp,
        p1, NN, GD, (long)HD * GD);

    agg1_k<<<EE / 8, 256>>>(ei, et);

    split_k<<<(int)(((long)NN * HD + 255) / 256), 256>>>(
        (const float*)hp, (__nv_bfloat16*)hhip, (__nv_bfloat16*)hlop, (long)NN * HD);

    // fused q, k, v, skip
    OutPack p2{};
    p2.d[0] = { (float*)qp, bq,    (long)HD };
    p2.d[1] = { (float*)kp, bk,    (long)HD };
    p2.d[2] = { (float*)vp, bv,    (long)HD };
    p2.d[3] = { out,        bskip, (long)HD };
    mmagemm_k<<<dim3(4, rowTiles), 256, SMEM_BYTES>>>(
        (const __nv_bfloat16*)hhip, (const __nv_bfloat16*)hlop,
        (const __nv_bfloat16*)wqkhp, (const __nv_bfloat16*)wqklp,
        p2, NN, HD, (long)HD * HD);

    // segment-softmax attention into out
    score_k<<<EE / 8, 256>>>(ei);
    agg2_k <<<EE / 8, 256>>>(ei, out);

    // batch norm + leaky relu (in-place on out)
    bnstats_k<<<512, 256>>>(out);
    bnfinal_k<<<1, HD>>>(gamma, beta);
    bnapply_k<<<(NN * HD) / 256, 256>>>(out);
}

// round 5
// speedup vs baseline: 2.9354x; 1.4158x over previous
#include <cuda_runtime.h>
#include <cuda_bf16.h>
#include <cstdint>

// ---------------------------------------------------------------------------
// GNN_6837587935613: RGCN(mean, R=8) -> TransformerConv(1 head) -> BN+LeakyReLU
// N=50000, E=800000, G_DIM=512, H1=H2=128, R=8
// Round 5: CSR-by-dst edge processing (atomic-free agg1 + single-pass fused
//          attention), k/v interleaved rows. GEMMs unchanged from R4.
// ---------------------------------------------------------------------------

#define NN   50000
#define NPAD 50176
#define EE   800000
#define GD   512
#define HD   128
#define RR   8
#define NBS  196   // ceil(NN/256) scan blocks

// ---- scratch (device globals) ----
__device__ float4   g_xW[(size_t)NN * 256];   // [N, R*128] f32
__device__ float4   g_h [(size_t)NN * 32];    // [N, 128]
__device__ float4   g_q [(size_t)NN * 32];
__device__ float4   g_kv[(size_t)NN * 64];    // [N, 256]: k row then v row
__device__ int      g_cnt[NN * RR];
__device__ int      g_deg[NN];
__device__ int      g_off[NN];
__device__ int      g_fill[NN];
__device__ int      g_bsum[256];
__device__ int      g_bsumx[256];
__device__ unsigned g_csr[EE];
__device__ float    g_bnsum[HD];
__device__ float    g_bnsq[HD];
__device__ float    g_scale[HD];
__device__ float    g_shift[HD];
__device__ int      g_idx64;

// bf16 split operands (row-padded so tile loads never go OOB)
__device__ __align__(128) __nv_bfloat16 g_Ahi[(size_t)NPAD * GD];
__device__ __align__(128) __nv_bfloat16 g_Alo[(size_t)NPAD * GD];
__device__ __align__(128) __nv_bfloat16 g_Hhi[(size_t)NPAD * HD];
__device__ __align__(128) __nv_bfloat16 g_Hlo[(size_t)NPAD * HD];
// K-major weights: g_Wall = [9][128][512] (8 relations + root), g_Wqkvs = [4][128][128]
__device__ __align__(128) __nv_bfloat16 g_Wall_hi[9 * HD * GD];
__device__ __align__(128) __nv_bfloat16 g_Wall_lo[9 * HD * GD];
__device__ __align__(128) __nv_bfloat16 g_Wqkvs_hi[4 * HD * HD];
__device__ __align__(128) __nv_bfloat16 g_Wqkvs_lo[4 * HD * HD];

// ---------------------------------------------------------------------------
__device__ __forceinline__ uint32_t smem_u32(const void* p) {
    uint32_t a;
    asm("{ .reg .u64 t; cvta.to.shared.u64 t, %1; cvt.u32.u64 %0, t; }"
        : "=r"(a) : "l"(p));
    return a;
}
#define SWZ(o) ((o) ^ (((o) >> 3) & 0x70))

#define CP_ASYNC16(dst, src) \
    asm volatile("cp.async.cg.shared.global [%0], [%1], 16;" :: "r"(dst), "l"(src))
#define CP_COMMIT()  asm volatile("cp.async.commit_group;" ::: "memory")
#define CP_WAIT0()   asm volatile("cp.async.wait_group 0;" ::: "memory")
#define CP_WAIT1()   asm volatile("cp.async.wait_group 1;" ::: "memory")

#define LDSM_X4(r, a)                                                        \
    asm volatile("ldmatrix.sync.aligned.m8n8.x4.shared.b16 {%0,%1,%2,%3}, [%4];" \
        : "=r"((r)[0]), "=r"((r)[1]), "=r"((r)[2]), "=r"((r)[3]) : "r"(a))

#define MMA16816(c, a, b0, b1)                                               \
    asm volatile("mma.sync.aligned.m16n8k16.row.col.f32.bf16.bf16.f32 "      \
        "{%0,%1,%2,%3}, {%4,%5,%6,%7}, {%8,%9}, {%0,%1,%2,%3};"              \
        : "+f"((c)[0]), "+f"((c)[1]), "+f"((c)[2]), "+f"((c)[3])             \
        : "r"((a)[0]), "r"((a)[1]), "r"((a)[2]), "r"((a)[3]), "r"(b0), "r"(b1))

struct OutDesc { float* C; const float* bias; long ldc; };
struct OutPack { OutDesc d[9]; };

// ---------------------------------------------------------------------------
// bf16 split GEMM via mma.sync, 3-stage cp.async pipeline (unchanged from R4)
// ---------------------------------------------------------------------------
__global__ void __launch_bounds__(256, 2) mmagemm_k(
    const __nv_bfloat16* __restrict__ Ahi, const __nv_bfloat16* __restrict__ Alo,
    const __nv_bfloat16* __restrict__ Ball_hi, const __nv_bfloat16* __restrict__ Ball_lo,
    OutPack outs, int M, int K, long bzStride)
{
    extern __shared__ char smem[];
    const uint32_t sb = smem_u32(smem);
    const int tid = threadIdx.x, lane = tid & 31, wid = tid >> 5;
    const int wm = wid & 3, wn = wid >> 2;
    const int z = blockIdx.x, row0 = blockIdx.y * 128;
    const __nv_bfloat16* Bh = Ball_hi + (long)z * bzStride;
    const __nv_bfloat16* Bl = Ball_lo + (long)z * bzStride;

    const int KC = K >> 6;
    const int NIT = 3 * KC;

    float acc[2][8][4];
#pragma unroll
    for (int i = 0; i < 2; i++)
#pragma unroll
        for (int j = 0; j < 8; j++)
#pragma unroll
            for (int c = 0; c < 4; c++) acc[i][j][c] = 0.f;

    const int cr = tid >> 3, cck = tid & 7;

    auto issue = [&](int it) {
        const int pass = it / KC;
        const int k0 = (it - pass * KC) * 64;
        const __nv_bfloat16* Ap = (pass == 1) ? Alo : Ahi;
        const __nv_bfloat16* Bp = (pass == 2) ? Bl : Bh;
        const uint32_t base = sb + (it % 3) * 32768;
#pragma unroll
        for (int i = 0; i < 4; i++) {
            const int r = cr + i * 32;
            CP_ASYNC16(base + SWZ(r * 128 + cck * 16),
                       Ap + (size_t)(row0 + r) * K + k0 + cck * 8);
            CP_ASYNC16(base + 16384 + SWZ(r * 128 + cck * 16),
                       Bp + (size_t)r * K + k0 + cck * 8);
        }
        CP_COMMIT();
    };

    issue(0);
    issue(1);
    for (int it = 0; it < NIT; ++it) {
        if (it + 1 < NIT) CP_WAIT1();
        else              CP_WAIT0();
        __syncthreads();
        if (it + 2 < NIT) issue(it + 2);

        const uint32_t Ab = sb + (it % 3) * 32768;
        const uint32_t Bb = Ab + 16384;
#pragma unroll
        for (int ks = 0; ks < 4; ks++) {
            uint32_t ra[2][4];
#pragma unroll
            for (int mi = 0; mi < 2; mi++) {
                const int r = wm * 32 + mi * 16 + (lane & 15);
                const int ck = ks * 2 + (lane >> 4);
                LDSM_X4(ra[mi], Ab + SWZ(r * 128 + ck * 16));
            }
            uint32_t rb[4][4];
#pragma unroll
            for (int g = 0; g < 4; g++) {
                const int nr = wn * 64 + g * 16 + ((lane & 7) | ((lane & 16) >> 1));
                const int ck = ks * 2 + ((lane >> 3) & 1);
                LDSM_X4(rb[g], Bb + SWZ(nr * 128 + ck * 16));
            }
#pragma unroll
            for (int mi = 0; mi < 2; mi++)
#pragma unroll
                for (int g = 0; g < 4; g++) {
                    MMA16816(acc[mi][2 * g + 0], ra[mi], rb[g][0], rb[g][1]);
                    MMA16816(acc[mi][2 * g + 1], ra[mi], rb[g][2], rb[g][3]);
                }
        }
    }

    float* C = outs.d[z].C;
    const float* bias = outs.d[z].bias;
    const long ldc = outs.d[z].ldc;
#pragma unroll
    for (int mi = 0; mi < 2; mi++) {
        const int rbase = row0 + wm * 32 + mi * 16 + (lane >> 2);
#pragma unroll
        for (int ni = 0; ni < 8; ni++) {
            const int cl = wn * 64 + ni * 8 + (lane & 3) * 2;
            float b0 = 0.f, b1 = 0.f;
            if (bias) { b0 = bias[cl]; b1 = bias[cl + 1]; }
            if (rbase < M) {
                float2 v = { acc[mi][ni][0] + b0, acc[mi][ni][1] + b1 };
                *(float2*)(C + (size_t)rbase * ldc + cl) = v;
            }
            if (rbase + 8 < M) {
                float2 v = { acc[mi][ni][2] + b0, acc[mi][ni][3] + b1 };
                *(float2*)(C + (size_t)(rbase + 8) * ldc + cl) = v;
            }
        }
    }
}

// ---------------------------------------------------------------------------
// fp32 -> bf16 hi/lo split + weight prep
// ---------------------------------------------------------------------------
__global__ void split_k(const float* __restrict__ s, __nv_bfloat16* __restrict__ hi,
                        __nv_bfloat16* __restrict__ lo, long n) {
    long i = (long)blockIdx.x * blockDim.x + threadIdx.x;
    if (i >= n) return;
    float v = s[i];
    __nv_bfloat16 h = __float2bfloat16(v);
    hi[i] = h;
    lo[i] = __float2bfloat16(v - __bfloat162float(h));
}

__device__ __forceinline__ void wsplit(__nv_bfloat16* hi, __nv_bfloat16* lo,
                                       long idx, float v) {
    __nv_bfloat16 h = __float2bfloat16(v);
    hi[idx] = h;
    lo[idx] = __float2bfloat16(v - __bfloat162float(h));
}

__global__ void prepw_k(const float* __restrict__ Wrel, const float* __restrict__ Wroot,
                        const float* __restrict__ Wq, const float* __restrict__ Wk,
                        const float* __restrict__ Wv, const float* __restrict__ Ws) {
    const int T0 = 9 * GD * HD;
    const int T1 = T0 + 4 * HD * HD;
    int i = blockIdx.x * blockDim.x + threadIdx.x;
    if (i >= T1) return;
    if (i < T0) {
        int z = i >> 16, rem = i & 65535;
        int k = rem >> 7, n = rem & 127;
        float v = (z < 8) ? Wrel[(long)z * 65536 + k * 128 + n] : Wroot[k * 128 + n];
        wsplit(g_Wall_hi, g_Wall_lo, (long)z * 65536 + n * 512 + k, v);
    } else {
        int j = i - T0;
        int m = j >> 14, jj = j & 16383;
        int k = jj >> 7, n = jj & 127;
        float v = (m == 0) ? Wq[jj] : (m == 1) ? Wk[jj] : (m == 2) ? Wv[jj] : Ws[jj];
        wsplit(g_Wqkvs_hi, g_Wqkvs_lo, (long)m * 16384 + n * 128 + k, v);
    }
}

// ---------------------------------------------------------------------------
// index handling, counts, CSR build
// ---------------------------------------------------------------------------
__device__ __forceinline__ int ldidx(const void* p, long i) {
    return g_idx64 ? (int)((const long long*)p)[i] : ((const int*)p)[i];
}

__global__ void detect_k(const unsigned* __restrict__ w) {
    if (blockIdx.x == 0 && threadIdx.x == 0) {
        int is64 = 1;
        for (int i = 0; i < 32; i++)
            if (w[2 * i + 1] != 0u) { is64 = 0; break; }
        g_idx64 = is64;
    }
}

__global__ void zero_k() {
    int i = blockIdx.x * blockDim.x + threadIdx.x;
    if (i < NN * RR) g_cnt[i] = 0;
    if (i < NN) g_fill[i] = 0;
    if (i < HD) { g_bnsum[i] = 0.f; g_bnsq[i] = 0.f; }
}

__global__ void count_k(const void* __restrict__ ei, const void* __restrict__ et) {
    int e = blockIdx.x * blockDim.x + threadIdx.x;
    if (e >= EE) return;
    int dst = ldidx(ei, (long)EE + e);
    int r   = ldidx(et, e);
    atomicAdd(&g_cnt[dst * RR + r], 1);
}

__global__ void degsum_k() {
    int i = blockIdx.x * blockDim.x + threadIdx.x;
    if (i >= NN) return;
    int d = 0;
#pragma unroll
    for (int r = 0; r < RR; r++) d += g_cnt[i * RR + r];
    g_deg[i] = d;
}

__global__ void scanA_k() {
    __shared__ int s[256];
    int i = blockIdx.x * 256 + threadIdx.x;
    s[threadIdx.x] = (i < NN) ? g_deg[i] : 0;
    __syncthreads();
    for (int st = 128; st; st >>= 1) {
        if (threadIdx.x < st) s[threadIdx.x] += s[threadIdx.x + st];
        __syncthreads();
    }
    if (threadIdx.x == 0) g_bsum[blockIdx.x] = s[0];
}

__global__ void scanB_k() {
    __shared__ int s[256];
    int v = (threadIdx.x < NBS) ? g_bsum[threadIdx.x] : 0;
    s[threadIdx.x] = v;
    __syncthreads();
    for (int st = 1; st < 256; st <<= 1) {
        int t = (threadIdx.x >= st) ? s[threadIdx.x - st] : 0;
        __syncthreads();
        s[threadIdx.x] += t;
        __syncthreads();
    }
    if (threadIdx.x < NBS) g_bsumx[threadIdx.x] = s[threadIdx.x] - v;
}

__global__ void scanC_k() {
    __shared__ int s[256];
    int i = blockIdx.x * 256 + threadIdx.x;
    int v = (i < NN) ? g_deg[i] : 0;
    s[threadIdx.x] = v;
    __syncthreads();
    for (int st = 1; st < 256; st <<= 1) {
        int t = (threadIdx.x >= st) ? s[threadIdx.x - st] : 0;
        __syncthreads();
        s[threadIdx.x] += t;
        __syncthreads();
    }
    if (i < NN) g_off[i] = g_bsumx[blockIdx.x] + s[threadIdx.x] - v;
}

__global__ void bucket_k(const void* __restrict__ ei, const void* __restrict__ et) {
    int e = blockIdx.x * blockDim.x + threadIdx.x;
    if (e >= EE) return;
    int src = ldidx(ei, e);
    int dst = ldidx(ei, (long)EE + e);
    int r   = ldidx(et, e);
    int pos = g_off[dst] + atomicAdd(&g_fill[dst], 1);
    g_csr[pos] = (unsigned)src | ((unsigned)r << 24);
}

// ---------------------------------------------------------------------------
// warp-per-dst RGCN aggregation (atomic-free)
// ---------------------------------------------------------------------------
__global__ void agg1csr_k() {
    int dst = (blockIdx.x * blockDim.x + threadIdx.x) >> 5;
    int lane = threadIdx.x & 31;
    if (dst >= NN) return;
    float invc = 0.f;
    if (lane < RR) {
        int c = g_cnt[dst * RR + lane];
        invc = 1.0f / (float)max(c, 1);
    }
    const int off = g_off[dst], deg = g_deg[dst];
    float4 acc = {0.f, 0.f, 0.f, 0.f};
    for (int base = 0; base < deg; base += 32) {
        unsigned pk = 0;
        int m = min(32, deg - base);
        if (lane < m) pk = g_csr[off + base + lane];
        for (int j = 0; j < m; j++) {
            unsigned p = __shfl_sync(0xffffffffu, pk, j);
            int src = p & 0xFFFFFF;
            int r   = p >> 24;
            float w = __shfl_sync(0xffffffffu, invc, r);
            float4 v = g_xW[(long)src * 256 + r * 32 + lane];
            acc.x += w * v.x; acc.y += w * v.y;
            acc.z += w * v.z; acc.w += w * v.w;
        }
    }
    float4 cur = g_h[(long)dst * 32 + lane];
    cur.x += acc.x; cur.y += acc.y; cur.z += acc.z; cur.w += acc.w;
    g_h[(long)dst * 32 + lane] = cur;
}

// ---------------------------------------------------------------------------
// warp-per-dst fused attention: score + exp + sum + weighted V, single pass
// ---------------------------------------------------------------------------
__global__ void attn_k(float* __restrict__ out) {
    int dst = (blockIdx.x * blockDim.x + threadIdx.x) >> 5;
    int lane = threadIdx.x & 31;
    if (dst >= NN) return;
    const float4 qv = g_q[(long)dst * 32 + lane];
    const int off = g_off[dst], deg = g_deg[dst];
    float4 accv = {0.f, 0.f, 0.f, 0.f};
    float ssum = 0.f;
    for (int base = 0; base < deg; base += 32) {
        unsigned pk = 0;
        int m = min(32, deg - base);
        if (lane < m) pk = g_csr[off + base + lane];
        for (int j = 0; j < m; j++) {
            unsigned p = __shfl_sync(0xffffffffu, pk, j);
            int src = (int)(p & 0xFFFFFF);
            float4 kv = g_kv[(long)src * 64 + lane];
            float d = qv.x * kv.x + qv.y * kv.y + qv.z * kv.z + qv.w * kv.w;
#pragma unroll
            for (int o = 16; o; o >>= 1) d += __shfl_xor_sync(0xffffffffu, d, o);
            float ex = expf(d * 0.08838834764831845f);  // 1/sqrt(128)
            float4 vv = g_kv[(long)src * 64 + 32 + lane];
            ssum += ex;
            accv.x += ex * vv.x; accv.y += ex * vv.y;
            accv.z += ex * vv.z; accv.w += ex * vv.w;
        }
    }
    float inv = 1.0f / fmaxf(ssum, 1e-16f);
    float4* op = (float4*)(out + (long)dst * 128) + lane;
    float4 cur = *op;
    cur.x += accv.x * inv; cur.y += accv.y * inv;
    cur.z += accv.z * inv; cur.w += accv.w * inv;
    *op = cur;
}

// ---------------------------------------------------------------------------
// batch norm
// ---------------------------------------------------------------------------
__global__ void bnstats_k(const float* __restrict__ x) {
    const int c = threadIdx.x & 127;
    const int rpb = blockDim.x >> 7;
    int row = blockIdx.x * rpb + (threadIdx.x >> 7);
    const int stride = gridDim.x * rpb;
    float s = 0.f, q = 0.f;
    for (; row < NN; row += stride) {
        float v = x[(long)row * HD + c];
        s += v; q += v * v;
    }
    __shared__ float sh[256], shq[256];
    sh[threadIdx.x] = s; shq[threadIdx.x] = q;
    __syncthreads();
    if (threadIdx.x < 128) {
        s = sh[threadIdx.x] + sh[threadIdx.x + 128];
        q = shq[threadIdx.x] + shq[threadIdx.x + 128];
        atomicAdd(&g_bnsum[c], s);
        atomicAdd(&g_bnsq[c], q);
    }
}

__global__ void bnfinal_k(const float* __restrict__ gamma, const float* __restrict__ beta) {
    int c = threadIdx.x;
    float mu  = g_bnsum[c] * (1.0f / NN);
    float var = g_bnsq[c] * (1.0f / NN) - mu * mu;
    var = fmaxf(var, 0.f);
    float inv = 1.0f / sqrtf(var + 1e-5f);
    float sc = gamma[c] * inv;
    g_scale[c] = sc;
    g_shift[c] = beta[c] - mu * sc;
}

__global__ void bnapply_k(float* __restrict__ out) {
    long i = (long)blockIdx.x * blockDim.x + threadIdx.x;
    int c = (int)(i & 127);
    float y = out[i] * g_scale[c] + g_shift[c];
    out[i] = (y >= 0.f) ? y : 0.01f * y;
}

// ---------------------------------------------------------------------------
extern "C" void kernel_launch(void* const* d_in, const int* in_sizes, int n_in,
                              void* d_out, int out_size)
{
    const float* x      = (const float*)d_in[0];
    const void*  ei     = d_in[1];
    const void*  et     = d_in[2];
    const float* W_rel  = (const float*)d_in[3];
    const float* W_root = (const float*)d_in[4];
    const float* b1     = (const float*)d_in[5];
    const float* Wq     = (const float*)d_in[6];
    const float* bq     = (const float*)d_in[7];
    const float* Wk     = (const float*)d_in[8];
    const float* bk     = (const float*)d_in[9];
    const float* Wv     = (const float*)d_in[10];
    const float* bv     = (const float*)d_in[11];
    const float* Wskip  = (const float*)d_in[12];
    const float* bskip  = (const float*)d_in[13];
    const float* gamma  = (const float*)d_in[14];
    const float* beta   = (const float*)d_in[15];
    float* out = (float*)d_out;

    void *xWp, *hp, *qp, *kvp;
    void *ahip, *alop, *hhip, *hlop, *wallhp, *walllp, *wqkhp, *wqklp;
    cudaGetSymbolAddress(&xWp, g_xW);
    cudaGetSymbolAddress(&hp,  g_h);
    cudaGetSymbolAddress(&qp,  g_q);
    cudaGetSymbolAddress(&kvp, g_kv);
    cudaGetSymbolAddress(&ahip, g_Ahi);
    cudaGetSymbolAddress(&alop, g_Alo);
    cudaGetSymbolAddress(&hhip, g_Hhi);
    cudaGetSymbolAddress(&hlop, g_Hlo);
    cudaGetSymbolAddress(&wallhp, g_Wall_hi);
    cudaGetSymbolAddress(&walllp, g_Wall_lo);
    cudaGetSymbolAddress(&wqkhp, g_Wqkvs_hi);
    cudaGetSymbolAddress(&wqklp, g_Wqkvs_lo);

    const int SMEM_BYTES = 3 * 32768;
    cudaFuncSetAttribute(mmagemm_k, cudaFuncAttributeMaxDynamicSharedMemorySize, SMEM_BYTES);

    const int rowTiles = (NN + 127) / 128;  // 391

    detect_k<<<1, 32>>>((const unsigned*)ei);
    zero_k<<<(NN * RR + 255) / 256, 256>>>();
    count_k<<<(EE + 255) / 256, 256>>>(ei, et);
    prepw_k<<<(9 * GD * HD + 4 * HD * HD + 255) / 256, 256>>>(
        W_rel, W_root, Wq, Wk, Wv, Wskip);
    split_k<<<(int)(((long)NN * GD + 255) / 256), 256>>>(
        x, (__nv_bfloat16*)ahip, (__nv_bfloat16*)alop, (long)NN * GD);

    // CSR by dst
    degsum_k<<<(NN + 255) / 256, 256>>>();
    scanA_k<<<NBS, 256>>>();
    scanB_k<<<1, 256>>>();
    scanC_k<<<NBS, 256>>>();
    bucket_k<<<(EE + 255) / 256, 256>>>(ei, et);

    // fused GEMM: z<8 -> xW columns (ldc 1024); z=8 -> h = x@Wroot + b1
    OutPack p1{};
    for (int zz = 0; zz < 8; zz++)
        p1.d[zz] = { (float*)xWp + zz * 128, nullptr, (long)(RR * HD) };
    p1.d[8] = { (float*)hp, b1, (long)HD };
    mmagemm_k<<<dim3(9, rowTiles), 256, SMEM_BYTES>>>(
        (const __nv_bfloat16*)ahip, (const __nv_bfloat16*)alop,
        (const __nv_bfloat16*)wallhp, (const __nv_bfloat16*)walllp,
        p1, NN, GD, (long)HD * GD);

    // atomic-free RGCN mean aggregation
    agg1csr_k<<<(NN * 32 + 255) / 256, 256>>>();

    split_k<<<(int)(((long)NN * HD + 255) / 256), 256>>>(
        (const float*)hp, (__nv_bfloat16*)hhip, (__nv_bfloat16*)hlop, (long)NN * HD);

    // fused q, k, v, skip (k/v interleaved into g_kv rows of 256)
    OutPack p2{};
    p2.d[0] = { (float*)qp,          bq,    (long)HD  };
    p2.d[1] = { (float*)kvp,         bk,    (long)256 };
    p2.d[2] = { (float*)kvp + 128,   bv,    (long)256 };
    p2.d[3] = { out,                 bskip, (long)HD  };
    mmagemm_k<<<dim3(4, rowTiles), 256, SMEM_BYTES>>>(
        (const __nv_bfloat16*)hhip, (const __nv_bfloat16*)hlop,
        (const __nv_bfloat16*)wqkhp, (const __nv_bfloat16*)wqklp,
        p2, NN, HD, (long)HD * HD);

    // fused single-pass attention (atomic-free)
    attn_k<<<(NN * 32 + 255) / 256, 256>>>(out);

    // batch norm + leaky relu (in-place on out)
    bnstats_k<<<512, 256>>>(out);
    bnfinal_k<<<1, HD>>>(gamma, beta);
    bnapply_k<<<(NN * HD) / 256, 256>>>(out);
}

// round 6
// speedup vs baseline: 5.4667x; 1.8623x over previous
#include <cuda_runtime.h>
#include <cuda_fp16.h>
#include <cuda_bf16.h>
#include <cstdint>

// ---------------------------------------------------------------------------
// GNN_6837587935613: RGCN(mean, R=8) -> TransformerConv(1 head) -> BN+LeakyReLU
// N=50000, E=800000, G_DIM=512, H1=H2=128, R=8
// Round 6: single-pass fp16 mma (error ~2e-4 << 1e-3 gate), fused h-convert,
//          2-edge-unrolled attention. CSR edge phase from R5.
// ---------------------------------------------------------------------------

#define NN   50000
#define NPAD 50176
#define EE   800000
#define GD   512
#define HD   128
#define RR   8
#define NBS  196   // ceil(NN/256) scan blocks

// ---- scratch (device globals) ----
__device__ float4   g_xW[(size_t)NN * 256];   // [N, R*128] f32
__device__ float4   g_h [(size_t)NN * 32];    // [N, 128]
__device__ float4   g_q [(size_t)NN * 32];
__device__ float4   g_kv[(size_t)NN * 64];    // [N, 256]: k row then v row
__device__ int      g_cnt[NN * RR];
__device__ int      g_deg[NN];
__device__ int      g_off[NN];
__device__ int      g_fill[NN];
__device__ int      g_bsum[256];
__device__ int      g_bsumx[256];
__device__ unsigned g_csr[EE];
__device__ float    g_bnsum[HD];
__device__ float    g_bnsq[HD];
__device__ float    g_scale[HD];
__device__ float    g_shift[HD];
__device__ int      g_idx64;

// fp16 operands (row-padded so tile loads never go OOB; padding stays zero)
__device__ __align__(128) __half g_Ah[(size_t)NPAD * GD];
__device__ __align__(128) __half g_Hh[(size_t)NPAD * HD];
// K-major fp16 weights: g_Wall = [9][128][512] (8 relations + root), g_Wqkvs = [4][128][128]
__device__ __align__(128) __half g_Wall[9 * HD * GD];
__device__ __align__(128) __half g_Wqkvs[4 * HD * HD];

// ---------------------------------------------------------------------------
__device__ __forceinline__ uint32_t smem_u32(const void* p) {
    uint32_t a;
    asm("{ .reg .u64 t; cvta.to.shared.u64 t, %1; cvt.u32.u64 %0, t; }"
        : "=r"(a) : "l"(p));
    return a;
}
#define SWZ(o) ((o) ^ (((o) >> 3) & 0x70))

#define CP_ASYNC16(dst, src) \
    asm volatile("cp.async.cg.shared.global [%0], [%1], 16;" :: "r"(dst), "l"(src))
#define CP_COMMIT()  asm volatile("cp.async.commit_group;" ::: "memory")
#define CP_WAIT0()   asm volatile("cp.async.wait_group 0;" ::: "memory")
#define CP_WAIT1()   asm volatile("cp.async.wait_group 1;" ::: "memory")

#define LDSM_X4(r, a)                                                        \
    asm volatile("ldmatrix.sync.aligned.m8n8.x4.shared.b16 {%0,%1,%2,%3}, [%4];" \
        : "=r"((r)[0]), "=r"((r)[1]), "=r"((r)[2]), "=r"((r)[3]) : "r"(a))

#define MMA16816(c, a, b0, b1)                                               \
    asm volatile("mma.sync.aligned.m16n8k16.row.col.f32.f16.f16.f32 "        \
        "{%0,%1,%2,%3}, {%4,%5,%6,%7}, {%8,%9}, {%0,%1,%2,%3};"              \
        : "+f"((c)[0]), "+f"((c)[1]), "+f"((c)[2]), "+f"((c)[3])             \
        : "r"((a)[0]), "r"((a)[1]), "r"((a)[2]), "r"((a)[3]), "r"(b0), "r"(b1))

struct OutDesc { float* C; const float* bias; long ldc; };
struct OutPack { OutDesc d[9]; };

// ---------------------------------------------------------------------------
// fp16 single-pass GEMM via mma.sync, 3-stage cp.async pipeline.
// C_z[row, n] = A[row,:K] @ B_z[n,:K]^T (B K-major), fp32 accumulate.
// grid = (Z, ceil(M/128)), block = 256 (8 warps: 4M x 2N), smem = 3*32KB.
// blockIdx.x = z (fast) so same-row-tile blocks share the A tile in L2.
// ---------------------------------------------------------------------------
__global__ void __launch_bounds__(256, 2) mmagemm_k(
    const __half* __restrict__ A, const __half* __restrict__ Ball,
    OutPack outs, int M, int K, long bzStride)
{
    extern __shared__ char smem[];
    const uint32_t sb = smem_u32(smem);
    const int tid = threadIdx.x, lane = tid & 31, wid = tid >> 5;
    const int wm = wid & 3, wn = wid >> 2;
    const int z = blockIdx.x, row0 = blockIdx.y * 128;
    const __half* B = Ball + (long)z * bzStride;

    const int NIT = K >> 6;      // 64-elem K chunks

    float acc[2][8][4];
#pragma unroll
    for (int i = 0; i < 2; i++)
#pragma unroll
        for (int j = 0; j < 8; j++)
#pragma unroll
            for (int c = 0; c < 4; c++) acc[i][j][c] = 0.f;

    const int cr = tid >> 3, cck = tid & 7;

    auto issue = [&](int it) {
        const int k0 = it * 64;
        const uint32_t base = sb + (it % 3) * 32768;
#pragma unroll
        for (int i = 0; i < 4; i++) {
            const int r = cr + i * 32;
            CP_ASYNC16(base + SWZ(r * 128 + cck * 16),
                       A + (size_t)(row0 + r) * K + k0 + cck * 8);
            CP_ASYNC16(base + 16384 + SWZ(r * 128 + cck * 16),
                       B + (size_t)r * K + k0 + cck * 8);
        }
        CP_COMMIT();
    };

    issue(0);
    if (NIT > 1) issue(1);
    for (int it = 0; it < NIT; ++it) {
        if (it + 1 < NIT) CP_WAIT1();
        else              CP_WAIT0();
        __syncthreads();
        if (it + 2 < NIT) issue(it + 2);

        const uint32_t Ab = sb + (it % 3) * 32768;
        const uint32_t Bb = Ab + 16384;
#pragma unroll
        for (int ks = 0; ks < 4; ks++) {
            uint32_t ra[2][4];
#pragma unroll
            for (int mi = 0; mi < 2; mi++) {
                const int r = wm * 32 + mi * 16 + (lane & 15);
                const int ck = ks * 2 + (lane >> 4);
                LDSM_X4(ra[mi], Ab + SWZ(r * 128 + ck * 16));
            }
            uint32_t rb[4][4];
#pragma unroll
            for (int g = 0; g < 4; g++) {
                const int nr = wn * 64 + g * 16 + ((lane & 7) | ((lane & 16) >> 1));
                const int ck = ks * 2 + ((lane >> 3) & 1);
                LDSM_X4(rb[g], Bb + SWZ(nr * 128 + ck * 16));
            }
#pragma unroll
            for (int mi = 0; mi < 2; mi++)
#pragma unroll
                for (int g = 0; g < 4; g++) {
                    MMA16816(acc[mi][2 * g + 0], ra[mi], rb[g][0], rb[g][1]);
                    MMA16816(acc[mi][2 * g + 1], ra[mi], rb[g][2], rb[g][3]);
                }
        }
        if (it + 1 < NIT) __syncthreads();
    }

    float* C = outs.d[z].C;
    const float* bias = outs.d[z].bias;
    const long ldc = outs.d[z].ldc;
#pragma unroll
    for (int mi = 0; mi < 2; mi++) {
        const int rbase = row0 + wm * 32 + mi * 16 + (lane >> 2);
#pragma unroll
        for (int ni = 0; ni < 8; ni++) {
            const int cl = wn * 64 + ni * 8 + (lane & 3) * 2;
            float b0 = 0.f, b1 = 0.f;
            if (bias) { b0 = bias[cl]; b1 = bias[cl + 1]; }
            if (rbase < M) {
                float2 v = { acc[mi][ni][0] + b0, acc[mi][ni][1] + b1 };
                *(float2*)(C + (size_t)rbase * ldc + cl) = v;
            }
            if (rbase + 8 < M) {
                float2 v = { acc[mi][ni][2] + b0, acc[mi][ni][3] + b1 };
                *(float2*)(C + (size_t)(rbase + 8) * ldc + cl) = v;
            }
        }
    }
}

// ---------------------------------------------------------------------------
// conversions
// ---------------------------------------------------------------------------
__global__ void cvt_k(const float* __restrict__ s, __half* __restrict__ d, long n) {
    long i = ((long)blockIdx.x * blockDim.x + threadIdx.x) * 4;
    if (i >= n) return;
    float4 v = *(const float4*)(s + i);
    __half2 a = __floats2half2_rn(v.x, v.y);
    __half2 b = __floats2half2_rn(v.z, v.w);
    *(__half2*)(d + i) = a;
    *(__half2*)(d + i + 2) = b;
}

// transpose + convert weights. g_Wall: z<8 from Wrel[z], z=8 from Wroot; g_Wqkvs.
__global__ void prepw_k(const float* __restrict__ Wrel, const float* __restrict__ Wroot,
                        const float* __restrict__ Wq, const float* __restrict__ Wk,
                        const float* __restrict__ Wv, const float* __restrict__ Ws) {
    const int T0 = 9 * GD * HD;
    const int T1 = T0 + 4 * HD * HD;
    int i = blockIdx.x * blockDim.x + threadIdx.x;
    if (i >= T1) return;
    if (i < T0) {
        int z = i >> 16, rem = i & 65535;
        int k = rem >> 7, n = rem & 127;
        float v = (z < 8) ? Wrel[(long)z * 65536 + k * 128 + n] : Wroot[k * 128 + n];
        g_Wall[(long)z * 65536 + n * 512 + k] = __float2half(v);
    } else {
        int j = i - T0;
        int m = j >> 14, jj = j & 16383;
        int k = jj >> 7, n = jj & 127;
        float v = (m == 0) ? Wq[jj] : (m == 1) ? Wk[jj] : (m == 2) ? Wv[jj] : Ws[jj];
        g_Wqkvs[(long)m * 16384 + n * 128 + k] = __float2half(v);
    }
}

// ---------------------------------------------------------------------------
// index handling, counts, CSR build
// ---------------------------------------------------------------------------
__device__ __forceinline__ int ldidx(const void* p, long i) {
    return g_idx64 ? (int)((const long long*)p)[i] : ((const int*)p)[i];
}

__global__ void detect_k(const unsigned* __restrict__ w) {
    if (blockIdx.x == 0 && threadIdx.x == 0) {
        int is64 = 1;
        for (int i = 0; i < 32; i++)
            if (w[2 * i + 1] != 0u) { is64 = 0; break; }
        g_idx64 = is64;
    }
}

__global__ void zero_k() {
    int i = blockIdx.x * blockDim.x + threadIdx.x;
    if (i < NN * RR) g_cnt[i] = 0;
    if (i < NN) g_fill[i] = 0;
    if (i < HD) { g_bnsum[i] = 0.f; g_bnsq[i] = 0.f; }
}

__global__ void count_k(const void* __restrict__ ei, const void* __restrict__ et) {
    int e = blockIdx.x * blockDim.x + threadIdx.x;
    if (e >= EE) return;
    int dst = ldidx(ei, (long)EE + e);
    int r   = ldidx(et, e);
    atomicAdd(&g_cnt[dst * RR + r], 1);
}

__global__ void degsum_k() {
    int i = blockIdx.x * blockDim.x + threadIdx.x;
    if (i >= NN) return;
    int d = 0;
#pragma unroll
    for (int r = 0; r < RR; r++) d += g_cnt[i * RR + r];
    g_deg[i] = d;
}

__global__ void scanA_k() {
    __shared__ int s[256];
    int i = blockIdx.x * 256 + threadIdx.x;
    s[threadIdx.x] = (i < NN) ? g_deg[i] : 0;
    __syncthreads();
    for (int st = 128; st; st >>= 1) {
        if (threadIdx.x < st) s[threadIdx.x] += s[threadIdx.x + st];
        __syncthreads();
    }
    if (threadIdx.x == 0) g_bsum[blockIdx.x] = s[0];
}

__global__ void scanB_k() {
    __shared__ int s[256];
    int v = (threadIdx.x < NBS) ? g_bsum[threadIdx.x] : 0;
    s[threadIdx.x] = v;
    __syncthreads();
    for (int st = 1; st < 256; st <<= 1) {
        int t = (threadIdx.x >= st) ? s[threadIdx.x - st] : 0;
        __syncthreads();
        s[threadIdx.x] += t;
        __syncthreads();
    }
    if (threadIdx.x < NBS) g_bsumx[threadIdx.x] = s[threadIdx.x] - v;
}

__global__ void scanC_k() {
    __shared__ int s[256];
    int i = blockIdx.x * 256 + threadIdx.x;
    int v = (i < NN) ? g_deg[i] : 0;
    s[threadIdx.x] = v;
    __syncthreads();
    for (int st = 1; st < 256; st <<= 1) {
        int t = (threadIdx.x >= st) ? s[threadIdx.x - st] : 0;
        __syncthreads();
        s[threadIdx.x] += t;
        __syncthreads();
    }
    if (i < NN) g_off[i] = g_bsumx[blockIdx.x] + s[threadIdx.x] - v;
}

__global__ void bucket_k(const void* __restrict__ ei, const void* __restrict__ et) {
    int e = blockIdx.x * blockDim.x + threadIdx.x;
    if (e >= EE) return;
    int src = ldidx(ei, e);
    int dst = ldidx(ei, (long)EE + e);
    int r   = ldidx(et, e);
    int pos = g_off[dst] + atomicAdd(&g_fill[dst], 1);
    g_csr[pos] = (unsigned)src | ((unsigned)r << 24);
}

// ---------------------------------------------------------------------------
// warp-per-dst RGCN aggregation (atomic-free) + fused h -> fp16 convert
// ---------------------------------------------------------------------------
__global__ void agg1csr_k() {
    int dst = (blockIdx.x * blockDim.x + threadIdx.x) >> 5;
    int lane = threadIdx.x & 31;
    if (dst >= NN) return;
    float invc = 0.f;
    if (lane < RR) {
        int c = g_cnt[dst * RR + lane];
        invc = 1.0f / (float)max(c, 1);
    }
    const int off = g_off[dst], deg = g_deg[dst];
    float4 acc = {0.f, 0.f, 0.f, 0.f};
    for (int base = 0; base < deg; base += 32) {
        unsigned pk = 0;
        int m = min(32, deg - base);
        if (lane < m) pk = g_csr[off + base + lane];
        for (int j = 0; j < m; j++) {
            unsigned p = __shfl_sync(0xffffffffu, pk, j);
            int src = p & 0xFFFFFF;
            int r   = p >> 24;
            float w = __shfl_sync(0xffffffffu, invc, r);
            float4 v = g_xW[(long)src * 256 + r * 32 + lane];
            acc.x += w * v.x; acc.y += w * v.y;
            acc.z += w * v.z; acc.w += w * v.w;
        }
    }
    float4 cur = g_h[(long)dst * 32 + lane];
    cur.x += acc.x; cur.y += acc.y; cur.z += acc.z; cur.w += acc.w;
    g_h[(long)dst * 32 + lane] = cur;
    // fused fp16 convert for the qkvs GEMM
    __half2 a = __floats2half2_rn(cur.x, cur.y);
    __half2 b = __floats2half2_rn(cur.z, cur.w);
    __half2* hp = (__half2*)(g_Hh + (size_t)dst * HD + lane * 4);
    hp[0] = a; hp[1] = b;
}

// ---------------------------------------------------------------------------
// warp-per-dst fused attention, 2-edge unrolled (independent shuffle chains)
// ---------------------------------------------------------------------------
__global__ void attn_k(float* __restrict__ out) {
    int dst = (blockIdx.x * blockDim.x + threadIdx.x) >> 5;
    int lane = threadIdx.x & 31;
    if (dst >= NN) return;
    const float4 qv = g_q[(long)dst * 32 + lane];
    const int off = g_off[dst], deg = g_deg[dst];
    float4 accv = {0.f, 0.f, 0.f, 0.f};
    float ssum = 0.f;
    const float sc = 0.08838834764831845f;  // 1/sqrt(128)
    for (int base = 0; base < deg; base += 32) {
        unsigned pk = 0;
        int m = min(32, deg - base);
        if (lane < m) pk = g_csr[off + base + lane];
        int j = 0;
        for (; j + 2 <= m; j += 2) {
            unsigned p0 = __shfl_sync(0xffffffffu, pk, j);
            unsigned p1 = __shfl_sync(0xffffffffu, pk, j + 1);
            long s0 = (long)(p0 & 0xFFFFFF), s1 = (long)(p1 & 0xFFFFFF);
            float4 k0 = g_kv[s0 * 64 + lane];
            float4 k1 = g_kv[s1 * 64 + lane];
            float d0 = qv.x * k0.x + qv.y * k0.y + qv.z * k0.z + qv.w * k0.w;
            float d1 = qv.x * k1.x + qv.y * k1.y + qv.z * k1.z + qv.w * k1.w;
#pragma unroll
            for (int o = 16; o; o >>= 1) {
                d0 += __shfl_xor_sync(0xffffffffu, d0, o);
                d1 += __shfl_xor_sync(0xffffffffu, d1, o);
            }
            float e0 = expf(d0 * sc), e1 = expf(d1 * sc);
            float4 v0 = g_kv[s0 * 64 + 32 + lane];
            float4 v1 = g_kv[s1 * 64 + 32 + lane];
            ssum += e0 + e1;
            accv.x += e0 * v0.x + e1 * v1.x;
            accv.y += e0 * v0.y + e1 * v1.y;
            accv.z += e0 * v0.z + e1 * v1.z;
            accv.w += e0 * v0.w + e1 * v1.w;
        }
        if (j < m) {
            unsigned p = __shfl_sync(0xffffffffu, pk, j);
            long src = (long)(p & 0xFFFFFF);
            float4 kv = g_kv[src * 64 + lane];
            float d = qv.x * kv.x + qv.y * kv.y + qv.z * kv.z + qv.w * kv.w;
#pragma unroll
            for (int o = 16; o; o >>= 1) d += __shfl_xor_sync(0xffffffffu, d, o);
            float ex = expf(d * sc);
            float4 vv = g_kv[src * 64 + 32 + lane];
            ssum += ex;
            accv.x += ex * vv.x; accv.y += ex * vv.y;
            accv.z += ex * vv.z; accv.w += ex * vv.w;
        }
    }
    float inv = 1.0f / fmaxf(ssum, 1e-16f);
    float4* op = (float4*)(out + (long)dst * 128) + lane;
    float4 cur = *op;
    cur.x += accv.x * inv; cur.y += accv.y * inv;
    cur.z += accv.z * inv; cur.w += accv.w * inv;
    *op = cur;
}

// ---------------------------------------------------------------------------
// batch norm
// ---------------------------------------------------------------------------
__global__ void bnstats_k(const float* __restrict__ x) {
    const int c = threadIdx.x & 127;
    const int rpb = blockDim.x >> 7;
    int row = blockIdx.x * rpb + (threadIdx.x >> 7);
    const int stride = gridDim.x * rpb;
    float s = 0.f, q = 0.f;
    for (; row < NN; row += stride) {
        float v = x[(long)row * HD + c];
        s += v; q += v * v;
    }
    __shared__ float sh[256], shq[256];
    sh[threadIdx.x] = s; shq[threadIdx.x] = q;
    __syncthreads();
    if (threadIdx.x < 128) {
        s = sh[threadIdx.x] + sh[threadIdx.x + 128];
        q = shq[threadIdx.x] + shq[threadIdx.x + 128];
        atomicAdd(&g_bnsum[c], s);
        atomicAdd(&g_bnsq[c], q);
    }
}

__global__ void bnfinal_k(const float* __restrict__ gamma, const float* __restrict__ beta) {
    int c = threadIdx.x;
    float mu  = g_bnsum[c] * (1.0f / NN);
    float var = g_bnsq[c] * (1.0f / NN) - mu * mu;
    var = fmaxf(var, 0.f);
    float inv = 1.0f / sqrtf(var + 1e-5f);
    float scv = gamma[c] * inv;
    g_scale[c] = scv;
    g_shift[c] = beta[c] - mu * scv;
}

__global__ void bnapply_k(float* __restrict__ out) {
    long i = (long)blockIdx.x * blockDim.x + threadIdx.x;
    int c = (int)(i & 127);
    float y = out[i] * g_scale[c] + g_shift[c];
    out[i] = (y >= 0.f) ? y : 0.01f * y;
}

// ---------------------------------------------------------------------------
extern "C" void kernel_launch(void* const* d_in, const int* in_sizes, int n_in,
                              void* d_out, int out_size)
{
    const float* x      = (const float*)d_in[0];
    const void*  ei     = d_in[1];
    const void*  et     = d_in[2];
    const float* W_rel  = (const float*)d_in[3];
    const float* W_root = (const float*)d_in[4];
    const float* b1     = (const float*)d_in[5];
    const float* Wq     = (const float*)d_in[6];
    const float* bq     = (const float*)d_in[7];
    const float* Wk     = (const float*)d_in[8];
    const float* bk     = (const float*)d_in[9];
    const float* Wv     = (const float*)d_in[10];
    const float* bv     = (const float*)d_in[11];
    const float* Wskip  = (const float*)d_in[12];
    const float* bskip  = (const float*)d_in[13];
    const float* gamma  = (const float*)d_in[14];
    const float* beta   = (const float*)d_in[15];
    float* out = (float*)d_out;

    void *xWp, *hp, *qp, *kvp, *ahp, *hhp, *wallp, *wqkp;
    cudaGetSymbolAddress(&xWp, g_xW);
    cudaGetSymbolAddress(&hp,  g_h);
    cudaGetSymbolAddress(&qp,  g_q);
    cudaGetSymbolAddress(&kvp, g_kv);
    cudaGetSymbolAddress(&ahp, g_Ah);
    cudaGetSymbolAddress(&hhp, g_Hh);
    cudaGetSymbolAddress(&wallp, g_Wall);
    cudaGetSymbolAddress(&wqkp, g_Wqkvs);

    const int SMEM_BYTES = 3 * 32768;
    cudaFuncSetAttribute(mmagemm_k, cudaFuncAttributeMaxDynamicSharedMemorySize, SMEM_BYTES);

    const int rowTiles = (NN + 127) / 128;  // 391

    detect_k<<<1, 32>>>((const unsigned*)ei);
    zero_k<<<(NN * RR + 255) / 256, 256>>>();
    count_k<<<(EE + 255) / 256, 256>>>(ei, et);
    prepw_k<<<(9 * GD * HD + 4 * HD * HD + 255) / 256, 256>>>(
        W_rel, W_root, Wq, Wk, Wv, Wskip);
    cvt_k<<<(int)(((long)NN * GD / 4 + 255) / 256), 256>>>(
        x, (__half*)ahp, (long)NN * GD);

    // CSR by dst
    degsum_k<<<(NN + 255) / 256, 256>>>();
    scanA_k<<<NBS, 256>>>();
    scanB_k<<<1, 256>>>();
    scanC_k<<<NBS, 256>>>();
    bucket_k<<<(EE + 255) / 256, 256>>>(ei, et);

    // fused GEMM: z<8 -> xW columns (ldc 1024); z=8 -> h = x@Wroot + b1
    OutPack p1{};
    for (int zz = 0; zz < 8; zz++)
        p1.d[zz] = { (float*)xWp + zz * 128, nullptr, (long)(RR * HD) };
    p1.d[8] = { (float*)hp, b1, (long)HD };
    mmagemm_k<<<dim3(9, rowTiles), 256, SMEM_BYTES>>>(
        (const __half*)ahp, (const __half*)wallp, p1, NN, GD, (long)HD * GD);

    // atomic-free RGCN mean aggregation + fused h->fp16
    agg1csr_k<<<(NN * 32 + 255) / 256, 256>>>();

    // fused q, k, v, skip (k/v interleaved into g_kv rows of 256)
    OutPack p2{};
    p2.d[0] = { (float*)qp,        bq,    (long)HD  };
    p2.d[1] = { (float*)kvp,       bk,    (long)256 };
    p2.d[2] = { (float*)kvp + 128, bv,    (long)256 };
    p2.d[3] = { out,               bskip, (long)HD  };
    mmagemm_k<<<dim3(4, rowTiles), 256, SMEM_BYTES>>>(
        (const __half*)hhp, (const __half*)wqkp, p2, NN, HD, (long)HD * HD);

    // fused single-pass attention (atomic-free)
    attn_k<<<(NN * 32 + 255) / 256, 256>>>(out);

    // batch norm + leaky relu (in-place on out)
    bnstats_k<<<512, 256>>>(out);
    bnfinal_k<<<1, HD>>>(gamma, beta);
    bnapply_k<<<(NN * HD) / 256, 256>>>(out);
}

// round 7
// speedup vs baseline: 5.6675x; 1.0367x over previous
#include <cuda_runtime.h>
#include <cuda_fp16.h>
#include <cstdint>

// ---------------------------------------------------------------------------
// GNN_6837587935613: RGCN(mean, R=8) -> TransformerConv(1 head) -> BN+LeakyReLU
// N=50000, E=800000, G_DIM=512, H1=H2=128, R=8
// Round 7: GEMM2 3-pass fp16 split (error ~0), xW + kv stored fp16 (half the
//          edge-phase traffic), interleaved kv rows, fused h-split in agg1.
// ---------------------------------------------------------------------------

#define NN   50000
#define NPAD 50176
#define EE   800000
#define GD   512
#define HD   128
#define RR   8
#define NBS  196   // ceil(NN/256) scan blocks

// ---- scratch (device globals) ----
__device__ __align__(128) __half g_xWh[(size_t)NN * 1024];  // [N, 8*128] fp16
__device__ float4   g_h [(size_t)NN * 32];    // [N, 128] f32 (root+bias)
__device__ float4   g_q [(size_t)NN * 32];    // [N, 128] f32
__device__ __align__(128) __half g_kvh[(size_t)NN * 256];   // [N][32 grp][k4,v4]
__device__ int      g_cnt[NN * RR];
__device__ int      g_deg[NN];
__device__ int      g_off[NN];
__device__ int      g_fill[NN];
__device__ int      g_bsum[256];
__device__ int      g_bsumx[256];
__device__ unsigned g_csr[EE];
__device__ float    g_bnsum[HD];
__device__ float    g_bnsq[HD];
__device__ float    g_scale[HD];
__device__ float    g_shift[HD];
__device__ int      g_idx64;

// fp16 operands (row-padded; padding stays zero from load-time .bss init)
__device__ __align__(128) __half g_Ah[(size_t)NPAD * GD];
__device__ __align__(128) __half g_Hh[(size_t)NPAD * HD];   // hi(h)
__device__ __align__(128) __half g_Hl[(size_t)NPAD * HD];   // lo(h)
// K-major fp16 weights
__device__ __align__(128) __half g_Wall[9 * HD * GD];       // 8 relations + root
__device__ __align__(128) __half g_Wqk_hi[4 * HD * HD];
__device__ __align__(128) __half g_Wqk_lo[4 * HD * HD];

// ---------------------------------------------------------------------------
__device__ __forceinline__ uint32_t smem_u32(const void* p) {
    uint32_t a;
    asm("{ .reg .u64 t; cvta.to.shared.u64 t, %1; cvt.u32.u64 %0, t; }"
        : "=r"(a) : "l"(p));
    return a;
}
#define SWZ(o) ((o) ^ (((o) >> 3) & 0x70))

#define CP_ASYNC16(dst, src) \
    asm volatile("cp.async.cg.shared.global [%0], [%1], 16;" :: "r"(dst), "l"(src))
#define CP_COMMIT()  asm volatile("cp.async.commit_group;" ::: "memory")
#define CP_WAIT0()   asm volatile("cp.async.wait_group 0;" ::: "memory")
#define CP_WAIT1()   asm volatile("cp.async.wait_group 1;" ::: "memory")

#define LDSM_X4(r, a)                                                        \
    asm volatile("ldmatrix.sync.aligned.m8n8.x4.shared.b16 {%0,%1,%2,%3}, [%4];" \
        : "=r"((r)[0]), "=r"((r)[1]), "=r"((r)[2]), "=r"((r)[3]) : "r"(a))

#define MMA16816(c, a, b0, b1)                                               \
    asm volatile("mma.sync.aligned.m16n8k16.row.col.f32.f16.f16.f32 "        \
        "{%0,%1,%2,%3}, {%4,%5,%6,%7}, {%8,%9}, {%0,%1,%2,%3};"              \
        : "+f"((c)[0]), "+f"((c)[1]), "+f"((c)[2]), "+f"((c)[3])             \
        : "r"((a)[0]), "r"((a)[1]), "r"((a)[2]), "r"((a)[3]), "r"(b0), "r"(b1))

// mode: 0 = f32 plain; 1 = fp16 plain (ldc in halves); 2 = fp16 kv k-slot;
//       3 = fp16 kv v-slot (kv row = 32 groups of [k0..k3, v0..v3])
struct OutDesc { void* C; const float* bias; long ldc; int mode; };
struct OutPack { OutDesc d[9]; };

// ---------------------------------------------------------------------------
// fp16 GEMM via mma.sync, 3-stage cp.async pipeline. NPASS=1: C = A@B^T.
// NPASS=3: C = Ahi@Bhi^T + Alo@Bhi^T + Ahi@Blo^T (fp32-accurate split).
// grid = (Z, ceil(M/128)), block = 256 (8 warps: 4M x 2N), smem = 3*32KB.
// ---------------------------------------------------------------------------
template <int NPASS>
__global__ void __launch_bounds__(256, 2) mmagemm_k(
    const __half* __restrict__ Ahi, const __half* __restrict__ Alo,
    const __half* __restrict__ Bhi, const __half* __restrict__ Blo,
    OutPack outs, int M, int K, long bzStride)
{
    extern __shared__ char smem[];
    const uint32_t sb = smem_u32(smem);
    const int tid = threadIdx.x, lane = tid & 31, wid = tid >> 5;
    const int wm = wid & 3, wn = wid >> 2;
    const int z = blockIdx.x, row0 = blockIdx.y * 128;
    const __half* Bh = Bhi + (long)z * bzStride;
    const __half* Bl = Blo ? Blo + (long)z * bzStride : nullptr;

    const int KC = K >> 6;
    const int NIT = NPASS * KC;

    float acc[2][8][4];
#pragma unroll
    for (int i = 0; i < 2; i++)
#pragma unroll
        for (int j = 0; j < 8; j++)
#pragma unroll
            for (int c = 0; c < 4; c++) acc[i][j][c] = 0.f;

    const int cr = tid >> 3, cck = tid & 7;

    auto issue = [&](int it) {
        const int pass = it / KC;
        const int k0 = (it - pass * KC) * 64;
        const __half* Ap = (NPASS == 3 && pass == 1) ? Alo : Ahi;
        const __half* Bp = (NPASS == 3 && pass == 2) ? Bl : Bh;
        const uint32_t base = sb + (it % 3) * 32768;
#pragma unroll
        for (int i = 0; i < 4; i++) {
            const int r = cr + i * 32;
            CP_ASYNC16(base + SWZ(r * 128 + cck * 16),
                       Ap + (size_t)(row0 + r) * K + k0 + cck * 8);
            CP_ASYNC16(base + 16384 + SWZ(r * 128 + cck * 16),
                       Bp + (size_t)r * K + k0 + cck * 8);
        }
        CP_COMMIT();
    };

    issue(0);
    if (NIT > 1) issue(1);
    for (int it = 0; it < NIT; ++it) {
        if (it + 1 < NIT) CP_WAIT1();
        else              CP_WAIT0();
        __syncthreads();
        if (it + 2 < NIT) issue(it + 2);

        const uint32_t Ab = sb + (it % 3) * 32768;
        const uint32_t Bb = Ab + 16384;
#pragma unroll
        for (int ks = 0; ks < 4; ks++) {
            uint32_t ra[2][4];
#pragma unroll
            for (int mi = 0; mi < 2; mi++) {
                const int r = wm * 32 + mi * 16 + (lane & 15);
                const int ck = ks * 2 + (lane >> 4);
                LDSM_X4(ra[mi], Ab + SWZ(r * 128 + ck * 16));
            }
            uint32_t rb[4][4];
#pragma unroll
            for (int g = 0; g < 4; g++) {
                const int nr = wn * 64 + g * 16 + ((lane & 7) | ((lane & 16) >> 1));
                const int ck = ks * 2 + ((lane >> 3) & 1);
                LDSM_X4(rb[g], Bb + SWZ(nr * 128 + ck * 16));
            }
#pragma unroll
            for (int mi = 0; mi < 2; mi++)
#pragma unroll
                for (int g = 0; g < 4; g++) {
                    MMA16816(acc[mi][2 * g + 0], ra[mi], rb[g][0], rb[g][1]);
                    MMA16816(acc[mi][2 * g + 1], ra[mi], rb[g][2], rb[g][3]);
                }
        }
        if (it + 1 < NIT) __syncthreads();
    }

    const OutDesc od = outs.d[z];
#pragma unroll
    for (int mi = 0; mi < 2; mi++) {
        const int r0e = row0 + wm * 32 + mi * 16 + (lane >> 2);
#pragma unroll
        for (int ni = 0; ni < 8; ni++) {
            const int cl = wn * 64 + ni * 8 + (lane & 3) * 2;
            float b0 = 0.f, b1 = 0.f;
            if (od.bias) { b0 = od.bias[cl]; b1 = od.bias[cl + 1]; }
#pragma unroll
            for (int hrow = 0; hrow < 2; hrow++) {
                const int row = r0e + hrow * 8;
                if (row >= M) continue;
                float v0 = acc[mi][ni][2 * hrow + 0] + b0;
                float v1 = acc[mi][ni][2 * hrow + 1] + b1;
                if (od.mode == 0) {
                    float2 v = { v0, v1 };
                    *(float2*)((float*)od.C + (size_t)row * od.ldc + cl) = v;
                } else {
                    __half2 hv = __floats2half2_rn(v0, v1);
                    size_t pos;
                    if (od.mode == 1)
                        pos = (size_t)row * od.ldc + cl;
                    else
                        pos = (size_t)row * 256 + ((cl >> 2) * 8) + (cl & 3)
                              + (od.mode == 3 ? 4 : 0);
                    *(__half2*)((__half*)od.C + pos) = hv;
                }
            }
        }
    }
}

// ---------------------------------------------------------------------------
// conversions / weight prep
// ---------------------------------------------------------------------------
__global__ void cvt_k(const float* __restrict__ s, __half* __restrict__ d, long n) {
    long i = ((long)blockIdx.x * blockDim.x + threadIdx.x) * 4;
    if (i >= n) return;
    float4 v = *(const float4*)(s + i);
    *(__half2*)(d + i)     = __floats2half2_rn(v.x, v.y);
    *(__half2*)(d + i + 2) = __floats2half2_rn(v.z, v.w);
}

__global__ void prepw_k(const float* __restrict__ Wrel, const float* __restrict__ Wroot,
                        const float* __restrict__ Wq, const float* __restrict__ Wk,
                        const float* __restrict__ Wv, const float* __restrict__ Ws) {
    const int T0 = 9 * GD * HD;
    const int T1 = T0 + 4 * HD * HD;
    int i = blockIdx.x * blockDim.x + threadIdx.x;
    if (i >= T1) return;
    if (i < T0) {
        int z = i >> 16, rem = i & 65535;
        int k = rem >> 7, n = rem & 127;
        float v = (z < 8) ? Wrel[(long)z * 65536 + k * 128 + n] : Wroot[k * 128 + n];
        g_Wall[(long)z * 65536 + n * 512 + k] = __float2half(v);
    } else {
        int j = i - T0;
        int m = j >> 14, jj = j & 16383;
        int k = jj >> 7, n = jj & 127;
        float v = (m == 0) ? Wq[jj] : (m == 1) ? Wk[jj] : (m == 2) ? Wv[jj] : Ws[jj];
        __half h = __float2half_rn(v);
        long idx = (long)m * 16384 + n * 128 + k;
        g_Wqk_hi[idx] = h;
        g_Wqk_lo[idx] = __float2half_rn(v - __half2float(h));
    }
}

// ---------------------------------------------------------------------------
// index handling, counts, CSR build
// ---------------------------------------------------------------------------
__device__ __forceinline__ int ldidx(const void* p, long i) {
    return g_idx64 ? (int)((const long long*)p)[i] : ((const int*)p)[i];
}

__global__ void detect_k(const unsigned* __restrict__ w) {
    if (blockIdx.x == 0 && threadIdx.x == 0) {
        int is64 = 1;
        for (int i = 0; i < 32; i++)
            if (w[2 * i + 1] != 0u) { is64 = 0; break; }
        g_idx64 = is64;
    }
}

__global__ void zero_k() {
    int i = blockIdx.x * blockDim.x + threadIdx.x;
    if (i < NN * RR) g_cnt[i] = 0;
    if (i < NN) g_fill[i] = 0;
    if (i < HD) { g_bnsum[i] = 0.f; g_bnsq[i] = 0.f; }
}

__global__ void count_k(const void* __restrict__ ei, const void* __restrict__ et) {
    int e = blockIdx.x * blockDim.x + threadIdx.x;
    if (e >= EE) return;
    int dst = ldidx(ei, (long)EE + e);
    int r   = ldidx(et, e);
    atomicAdd(&g_cnt[dst * RR + r], 1);
}

__global__ void degsum_k() {
    int i = blockIdx.x * blockDim.x + threadIdx.x;
    if (i >= NN) return;
    int d = 0;
#pragma unroll
    for (int r = 0; r < RR; r++) d += g_cnt[i * RR + r];
    g_deg[i] = d;
}

__global__ void scanA_k() {
    __shared__ int s[256];
    int i = blockIdx.x * 256 + threadIdx.x;
    s[threadIdx.x] = (i < NN) ? g_deg[i] : 0;
    __syncthreads();
    for (int st = 128; st; st >>= 1) {
        if (threadIdx.x < st) s[threadIdx.x] += s[threadIdx.x + st];
        __syncthreads();
    }
    if (threadIdx.x == 0) g_bsum[blockIdx.x] = s[0];
}

__global__ void scanB_k() {
    __shared__ int s[256];
    int v = (threadIdx.x < NBS) ? g_bsum[threadIdx.x] : 0;
    s[threadIdx.x] = v;
    __syncthreads();
    for (int st = 1; st < 256; st <<= 1) {
        int t = (threadIdx.x >= st) ? s[threadIdx.x - st] : 0;
        __syncthreads();
        s[threadIdx.x] += t;
        __syncthreads();
    }
    if (threadIdx.x < NBS) g_bsumx[threadIdx.x] = s[threadIdx.x] - v;
}

__global__ void scanC_k() {
    __shared__ int s[256];
    int i = blockIdx.x * 256 + threadIdx.x;
    int v = (i < NN) ? g_deg[i] : 0;
    s[threadIdx.x] = v;
    __syncthreads();
    for (int st = 1; st < 256; st <<= 1) {
        int t = (threadIdx.x >= st) ? s[threadIdx.x - st] : 0;
        __syncthreads();
        s[threadIdx.x] += t;
        __syncthreads();
    }
    if (i < NN) g_off[i] = g_bsumx[blockIdx.x] + s[threadIdx.x] - v;
}

__global__ void bucket_k(const void* __restrict__ ei, const void* __restrict__ et) {
    int e = blockIdx.x * blockDim.x + threadIdx.x;
    if (e >= EE) return;
    int src = ldidx(ei, e);
    int dst = ldidx(ei, (long)EE + e);
    int r   = ldidx(et, e);
    int pos = g_off[dst] + atomicAdd(&g_fill[dst], 1);
    g_csr[pos] = (unsigned)src | ((unsigned)r << 24);
}

// ---------------------------------------------------------------------------
// warp-per-dst RGCN aggregation (fp16 gather, 2-edge unroll) + fused h split
// ---------------------------------------------------------------------------
__global__ void agg1csr_k() {
    int dst = (blockIdx.x * blockDim.x + threadIdx.x) >> 5;
    int lane = threadIdx.x & 31;
    if (dst >= NN) return;
    float invc = 0.f;
    if (lane < RR) {
        int c = g_cnt[dst * RR + lane];
        invc = 1.0f / (float)max(c, 1);
    }
    const int off = g_off[dst], deg = g_deg[dst];
    float4 acc = {0.f, 0.f, 0.f, 0.f};
    for (int base = 0; base < deg; base += 32) {
        unsigned pk = 0;
        int m = min(32, deg - base);
        if (lane < m) pk = g_csr[off + base + lane];
        int j = 0;
        for (; j + 2 <= m; j += 2) {
            unsigned p0 = __shfl_sync(0xffffffffu, pk, j);
            unsigned p1 = __shfl_sync(0xffffffffu, pk, j + 1);
            long s0 = (long)(p0 & 0xFFFFFF), s1 = (long)(p1 & 0xFFFFFF);
            int r0 = p0 >> 24, r1 = p1 >> 24;
            float w0 = __shfl_sync(0xffffffffu, invc, r0);
            float w1 = __shfl_sync(0xffffffffu, invc, r1);
            uint2 m0 = *(const uint2*)(g_xWh + s0 * 1024 + r0 * 128 + lane * 4);
            uint2 m1 = *(const uint2*)(g_xWh + s1 * 1024 + r1 * 128 + lane * 4);
            float2 a0 = __half22float2(*(__half2*)&m0.x);
            float2 b0 = __half22float2(*(__half2*)&m0.y);
            float2 a1 = __half22float2(*(__half2*)&m1.x);
            float2 b1 = __half22float2(*(__half2*)&m1.y);
            acc.x += w0 * a0.x + w1 * a1.x;
            acc.y += w0 * a0.y + w1 * a1.y;
            acc.z += w0 * b0.x + w1 * b1.x;
            acc.w += w0 * b0.y + w1 * b1.y;
        }
        if (j < m) {
            unsigned p = __shfl_sync(0xffffffffu, pk, j);
            long s0 = (long)(p & 0xFFFFFF);
            int r0 = p >> 24;
            float w0 = __shfl_sync(0xffffffffu, invc, r0);
            uint2 m0 = *(const uint2*)(g_xWh + s0 * 1024 + r0 * 128 + lane * 4);
            float2 a0 = __half22float2(*(__half2*)&m0.x);
            float2 b0 = __half22float2(*(__half2*)&m0.y);
            acc.x += w0 * a0.x; acc.y += w0 * a0.y;
            acc.z += w0 * b0.x; acc.w += w0 * b0.y;
        }
    }
    float4 cur = g_h[(long)dst * 32 + lane];
    cur.x += acc.x; cur.y += acc.y; cur.z += acc.z; cur.w += acc.w;
    // fused fp16 hi/lo split of h for the 3-pass qkvs GEMM
    __half hx = __float2half_rn(cur.x), hy = __float2half_rn(cur.y);
    __half hz = __float2half_rn(cur.z), hw = __float2half_rn(cur.w);
    __half2* hp = (__half2*)(g_Hh + (size_t)dst * HD + lane * 4);
    hp[0] = __half2{hx, hy}; hp[1] = __half2{hz, hw};
    __half2* lp = (__half2*)(g_Hl + (size_t)dst * HD + lane * 4);
    lp[0] = __floats2half2_rn(cur.x - __half2float(hx), cur.y - __half2float(hy));
    lp[1] = __floats2half2_rn(cur.z - __half2float(hz), cur.w - __half2float(hw));
}

// ---------------------------------------------------------------------------
// warp-per-dst fused attention: one 16B load/lane/edge (k+v interleaved fp16)
// ---------------------------------------------------------------------------
__global__ void attn_k(float* __restrict__ out) {
    int dst = (blockIdx.x * blockDim.x + threadIdx.x) >> 5;
    int lane = threadIdx.x & 31;
    if (dst >= NN) return;
    const float4 qv = g_q[(long)dst * 32 + lane];   // channels 4*lane..4*lane+3
    const int off = g_off[dst], deg = g_deg[dst];
    float4 accv = {0.f, 0.f, 0.f, 0.f};
    float ssum = 0.f;
    const float sc = 0.08838834764831845f;  // 1/sqrt(128)
    for (int base = 0; base < deg; base += 32) {
        unsigned pk = 0;
        int m = min(32, deg - base);
        if (lane < m) pk = g_csr[off + base + lane];
        int j = 0;
        for (; j + 2 <= m; j += 2) {
            unsigned p0 = __shfl_sync(0xffffffffu, pk, j);
            unsigned p1 = __shfl_sync(0xffffffffu, pk, j + 1);
            long s0 = (long)(p0 & 0xFFFFFF), s1 = (long)(p1 & 0xFFFFFF);
            uint4 r0 = *(const uint4*)(g_kvh + s0 * 256 + lane * 8);
            uint4 r1 = *(const uint4*)(g_kvh + s1 * 256 + lane * 8);
            float2 ka0 = __half22float2(*(__half2*)&r0.x);
            float2 kb0 = __half22float2(*(__half2*)&r0.y);
            float2 ka1 = __half22float2(*(__half2*)&r1.x);
            float2 kb1 = __half22float2(*(__half2*)&r1.y);
            float d0 = qv.x * ka0.x + qv.y * ka0.y + qv.z * kb0.x + qv.w * kb0.y;
            float d1 = qv.x * ka1.x + qv.y * ka1.y + qv.z * kb1.x + qv.w * kb1.y;
#pragma unroll
            for (int o = 16; o; o >>= 1) {
                d0 += __shfl_xor_sync(0xffffffffu, d0, o);
                d1 += __shfl_xor_sync(0xffffffffu, d1, o);
            }
            float e0 = expf(d0 * sc), e1 = expf(d1 * sc);
            float2 va0 = __half22float2(*(__half2*)&r0.z);
            float2 vb0 = __half22float2(*(__half2*)&r0.w);
            float2 va1 = __half22float2(*(__half2*)&r1.z);
            float2 vb1 = __half22float2(*(__half2*)&r1.w);
            ssum += e0 + e1;
            accv.x += e0 * va0.x + e1 * va1.x;
            accv.y += e0 * va0.y + e1 * va1.y;
            accv.z += e0 * vb0.x + e1 * vb1.x;
            accv.w += e0 * vb0.y + e1 * vb1.y;
        }
        if (j < m) {
            unsigned p = __shfl_sync(0xffffffffu, pk, j);
            long s0 = (long)(p & 0xFFFFFF);
            uint4 r0 = *(const uint4*)(g_kvh + s0 * 256 + lane * 8);
            float2 ka0 = __half22float2(*(__half2*)&r0.x);
            float2 kb0 = __half22float2(*(__half2*)&r0.y);
            float d0 = qv.x * ka0.x + qv.y * ka0.y + qv.z * kb0.x + qv.w * kb0.y;
#pragma unroll
            for (int o = 16; o; o >>= 1) d0 += __shfl_xor_sync(0xffffffffu, d0, o);
            float e0 = expf(d0 * sc);
            float2 va0 = __half22float2(*(__half2*)&r0.z);
            float2 vb0 = __half22float2(*(__half2*)&r0.w);
            ssum += e0;
            accv.x += e0 * va0.x; accv.y += e0 * va0.y;
            accv.z += e0 * vb0.x; accv.w += e0 * vb0.y;
        }
    }
    float inv = 1.0f / fmaxf(ssum, 1e-16f);
    float4* op = (float4*)(out + (long)dst * 128) + lane;
    float4 cur = *op;
    cur.x += accv.x * inv; cur.y += accv.y * inv;
    cur.z += accv.z * inv; cur.w += accv.w * inv;
    *op = cur;
}

// ---------------------------------------------------------------------------
// batch norm
// ---------------------------------------------------------------------------
__global__ void bnstats_k(const float* __restrict__ x) {
    const int c = threadIdx.x & 127;
    const int rpb = blockDim.x >> 7;
    int row = blockIdx.x * rpb + (threadIdx.x >> 7);
    const int stride = gridDim.x * rpb;
    float s = 0.f, q = 0.f;
    for (; row < NN; row += stride) {
        float v = x[(long)row * HD + c];
        s += v; q += v * v;
    }
    __shared__ float sh[256], shq[256];
    sh[threadIdx.x] = s; shq[threadIdx.x] = q;
    __syncthreads();
    if (threadIdx.x < 128) {
        s = sh[threadIdx.x] + sh[threadIdx.x + 128];
        q = shq[threadIdx.x] + shq[threadIdx.x + 128];
        atomicAdd(&g_bnsum[c], s);
        atomicAdd(&g_bnsq[c], q);
    }
}

__global__ void bnfinal_k(const float* __restrict__ gamma, const float* __restrict__ beta) {
    int c = threadIdx.x;
    float mu  = g_bnsum[c] * (1.0f / NN);
    float var = g_bnsq[c] * (1.0f / NN) - mu * mu;
    var = fmaxf(var, 0.f);
    float inv = 1.0f / sqrtf(var + 1e-5f);
    float scv = gamma[c] * inv;
    g_scale[c] = scv;
    g_shift[c] = beta[c] - mu * scv;
}

__global__ void bnapply_k(float* __restrict__ out) {
    long i = (long)blockIdx.x * blockDim.x + threadIdx.x;
    int c = (int)(i & 127);
    float y = out[i] * g_scale[c] + g_shift[c];
    out[i] = (y >= 0.f) ? y : 0.01f * y;
}

// ---------------------------------------------------------------------------
extern "C" void kernel_launch(void* const* d_in, const int* in_sizes, int n_in,
                              void* d_out, int out_size)
{
    const float* x      = (const float*)d_in[0];
    const void*  ei     = d_in[1];
    const void*  et     = d_in[2];
    const float* W_rel  = (const float*)d_in[3];
    const float* W_root = (const float*)d_in[4];
    const float* b1     = (const float*)d_in[5];
    const float* Wq     = (const float*)d_in[6];
    const float* bq     = (const float*)d_in[7];
    const float* Wk     = (const float*)d_in[8];
    const float* bk     = (const float*)d_in[9];
    const float* Wv     = (const float*)d_in[10];
    const float* bv     = (const float*)d_in[11];
    const float* Wskip  = (const float*)d_in[12];
    const float* bskip  = (const float*)d_in[13];
    const float* gamma  = (const float*)d_in[14];
    const float* beta   = (const float*)d_in[15];
    float* out = (float*)d_out;

    void *xwhp, *hp, *qp, *kvp, *ahp, *hhp, *hlp, *wallp, *wqhp, *wqlp;
    cudaGetSymbolAddress(&xwhp, g_xWh);
    cudaGetSymbolAddress(&hp,  g_h);
    cudaGetSymbolAddress(&qp,  g_q);
    cudaGetSymbolAddress(&kvp, g_kvh);
    cudaGetSymbolAddress(&ahp, g_Ah);
    cudaGetSymbolAddress(&hhp, g_Hh);
    cudaGetSymbolAddress(&hlp, g_Hl);
    cudaGetSymbolAddress(&wallp, g_Wall);
    cudaGetSymbolAddress(&wqhp, g_Wqk_hi);
    cudaGetSymbolAddress(&wqlp, g_Wqk_lo);

    const int SMEM_BYTES = 3 * 32768;
    cudaFuncSetAttribute(mmagemm_k<1>, cudaFuncAttributeMaxDynamicSharedMemorySize, SMEM_BYTES);
    cudaFuncSetAttribute(mmagemm_k<3>, cudaFuncAttributeMaxDynamicSharedMemorySize, SMEM_BYTES);

    const int rowTiles = (NN + 127) / 128;  // 391

    detect_k<<<1, 32>>>((const unsigned*)ei);
    zero_k<<<(NN * RR + 255) / 256, 256>>>();
    count_k<<<(EE + 255) / 256, 256>>>(ei, et);
    prepw_k<<<(9 * GD * HD + 4 * HD * HD + 255) / 256, 256>>>(
        W_rel, W_root, Wq, Wk, Wv, Wskip);
    cvt_k<<<(int)(((long)NN * GD / 4 + 255) / 256), 256>>>(
        x, (__half*)ahp, (long)NN * GD);

    // CSR by dst
    degsum_k<<<(NN + 255) / 256, 256>>>();
    scanA_k<<<NBS, 256>>>();
    scanB_k<<<1, 256>>>();
    scanC_k<<<NBS, 256>>>();
    bucket_k<<<(EE + 255) / 256, 256>>>(ei, et);

    // GEMM1 (single-pass fp16): z<8 -> xW fp16 (ldc 1024 halves); z=8 -> h f32
    OutPack p1{};
    for (int zz = 0; zz < 8; zz++)
        p1.d[zz] = { (void*)((__half*)xwhp + zz * 128), nullptr, 1024, 1 };
    p1.d[8] = { hp, b1, (long)HD, 0 };
    mmagemm_k<1><<<dim3(9, rowTiles), 256, SMEM_BYTES>>>(
        (const __half*)ahp, nullptr, (const __half*)wallp, nullptr,
        p1, NN, GD, (long)HD * GD);

    // RGCN mean aggregation (fp16 gather) + fused h hi/lo split
    agg1csr_k<<<(NN * 32 + 255) / 256, 256>>>();

    // GEMM2 (3-pass fp16 split): q f32, k/v fp16 interleaved, skip -> out f32
    OutPack p2{};
    p2.d[0] = { qp,  bq,    (long)HD, 0 };
    p2.d[1] = { kvp, bk,    256,      2 };
    p2.d[2] = { kvp, bv,    256,      3 };
    p2.d[3] = { out, bskip, (long)HD, 0 };
    mmagemm_k<3><<<dim3(4, rowTiles), 256, SMEM_BYTES>>>(
        (const __half*)hhp, (const __half*)hlp,
        (const __half*)wqhp, (const __half*)wqlp,
        p2, NN, HD, (long)HD * HD);

    // fused single-pass attention (atomic-free, fp16 kv)
    attn_k<<<(NN * 32 + 255) / 256, 256>>>(out);

    // batch norm + leaky relu (in-place on out)
    bnstats_k<<<512, 256>>>(out);
    bnfinal_k<<<1, HD>>>(gamma, beta);
    bnapply_k<<<(NN * HD) / 256, 256>>>(out);
}

// round 8
// speedup vs baseline: 5.7539x; 1.0152x over previous
#include <cuda_runtime.h>
#include <cuda_fp16.h>
#include <cstdint>

// ---------------------------------------------------------------------------
// GNN_6837587935613: RGCN(mean, R=8) -> TransformerConv(1 head) -> BN+LeakyReLU
// N=50000, E=800000, G_DIM=512, H1=H2=128, R=8
// Round 8: 4-edge-unrolled edge kernels (latency chains /4), BN stats fused
//          into attention epilogue. GEMMs unchanged from R7.
// ---------------------------------------------------------------------------

#define NN   50000
#define NPAD 50176
#define EE   800000
#define GD   512
#define HD   128
#define RR   8
#define NBS  196   // ceil(NN/256) scan blocks

// ---- scratch (device globals) ----
__device__ __align__(128) __half g_xWh[(size_t)NN * 1024];  // [N, 8*128] fp16
__device__ float4   g_h [(size_t)NN * 32];    // [N, 128] f32 (root+bias)
__device__ float4   g_q [(size_t)NN * 32];    // [N, 128] f32
__device__ __align__(128) __half g_kvh[(size_t)NN * 256];   // [N][32 grp][k4,v4]
__device__ int      g_cnt[NN * RR];
__device__ int      g_deg[NN];
__device__ int      g_off[NN];
__device__ int      g_fill[NN];
__device__ int      g_bsum[256];
__device__ int      g_bsumx[256];
__device__ unsigned g_csr[EE];
__device__ float    g_bnsum[HD];
__device__ float    g_bnsq[HD];
__device__ float    g_scale[HD];
__device__ float    g_shift[HD];
__device__ int      g_idx64;

// fp16 operands (row-padded; padding stays zero from load-time .bss init)
__device__ __align__(128) __half g_Ah[(size_t)NPAD * GD];
__device__ __align__(128) __half g_Hh[(size_t)NPAD * HD];   // hi(h)
__device__ __align__(128) __half g_Hl[(size_t)NPAD * HD];   // lo(h)
// K-major fp16 weights
__device__ __align__(128) __half g_Wall[9 * HD * GD];       // 8 relations + root
__device__ __align__(128) __half g_Wqk_hi[4 * HD * HD];
__device__ __align__(128) __half g_Wqk_lo[4 * HD * HD];

// ---------------------------------------------------------------------------
__device__ __forceinline__ uint32_t smem_u32(const void* p) {
    uint32_t a;
    asm("{ .reg .u64 t; cvta.to.shared.u64 t, %1; cvt.u32.u64 %0, t; }"
        : "=r"(a) : "l"(p));
    return a;
}
#define SWZ(o) ((o) ^ (((o) >> 3) & 0x70))

#define CP_ASYNC16(dst, src) \
    asm volatile("cp.async.cg.shared.global [%0], [%1], 16;" :: "r"(dst), "l"(src))
#define CP_COMMIT()  asm volatile("cp.async.commit_group;" ::: "memory")
#define CP_WAIT0()   asm volatile("cp.async.wait_group 0;" ::: "memory")
#define CP_WAIT1()   asm volatile("cp.async.wait_group 1;" ::: "memory")

#define LDSM_X4(r, a)                                                        \
    asm volatile("ldmatrix.sync.aligned.m8n8.x4.shared.b16 {%0,%1,%2,%3}, [%4];" \
        : "=r"((r)[0]), "=r"((r)[1]), "=r"((r)[2]), "=r"((r)[3]) : "r"(a))

#define MMA16816(c, a, b0, b1)                                               \
    asm volatile("mma.sync.aligned.m16n8k16.row.col.f32.f16.f16.f32 "        \
        "{%0,%1,%2,%3}, {%4,%5,%6,%7}, {%8,%9}, {%0,%1,%2,%3};"              \
        : "+f"((c)[0]), "+f"((c)[1]), "+f"((c)[2]), "+f"((c)[3])             \
        : "r"((a)[0]), "r"((a)[1]), "r"((a)[2]), "r"((a)[3]), "r"(b0), "r"(b1))

// mode: 0 = f32 plain; 1 = fp16 plain (ldc in halves); 2 = fp16 kv k-slot;
//       3 = fp16 kv v-slot (kv row = 32 groups of [k0..k3, v0..v3])
struct OutDesc { void* C; const float* bias; long ldc; int mode; };
struct OutPack { OutDesc d[9]; };

// ---------------------------------------------------------------------------
// fp16 GEMM via mma.sync, 3-stage cp.async pipeline. NPASS=1: C = A@B^T.
// NPASS=3: C = Ahi@Bhi^T + Alo@Bhi^T + Ahi@Blo^T (fp32-accurate split).
// grid = (Z, ceil(M/128)), block = 256 (8 warps: 4M x 2N), smem = 3*32KB.
// ---------------------------------------------------------------------------
template <int NPASS>
__global__ void __launch_bounds__(256, 2) mmagemm_k(
    const __half* __restrict__ Ahi, const __half* __restrict__ Alo,
    const __half* __restrict__ Bhi, const __half* __restrict__ Blo,
    OutPack outs, int M, int K, long bzStride)
{
    extern __shared__ char smem[];
    const uint32_t sb = smem_u32(smem);
    const int tid = threadIdx.x, lane = tid & 31, wid = tid >> 5;
    const int wm = wid & 3, wn = wid >> 2;
    const int z = blockIdx.x, row0 = blockIdx.y * 128;
    const __half* Bh = Bhi + (long)z * bzStride;
    const __half* Bl = Blo ? Blo + (long)z * bzStride : nullptr;

    const int KC = K >> 6;
    const int NIT = NPASS * KC;

    float acc[2][8][4];
#pragma unroll
    for (int i = 0; i < 2; i++)
#pragma unroll
        for (int j = 0; j < 8; j++)
#pragma unroll
            for (int c = 0; c < 4; c++) acc[i][j][c] = 0.f;

    const int cr = tid >> 3, cck = tid & 7;

    auto issue = [&](int it) {
        const int pass = it / KC;
        const int k0 = (it - pass * KC) * 64;
        const __half* Ap = (NPASS == 3 && pass == 1) ? Alo : Ahi;
        const __half* Bp = (NPASS == 3 && pass == 2) ? Bl : Bh;
        const uint32_t base = sb + (it % 3) * 32768;
#pragma unroll
        for (int i = 0; i < 4; i++) {
            const int r = cr + i * 32;
            CP_ASYNC16(base + SWZ(r * 128 + cck * 16),
                       Ap + (size_t)(row0 + r) * K + k0 + cck * 8);
            CP_ASYNC16(base + 16384 + SWZ(r * 128 + cck * 16),
                       Bp + (size_t)r * K + k0 + cck * 8);
        }
        CP_COMMIT();
    };

    issue(0);
    if (NIT > 1) issue(1);
    for (int it = 0; it < NIT; ++it) {
        if (it + 1 < NIT) CP_WAIT1();
        else              CP_WAIT0();
        __syncthreads();
        if (it + 2 < NIT) issue(it + 2);

        const uint32_t Ab = sb + (it % 3) * 32768;
        const uint32_t Bb = Ab + 16384;
#pragma unroll
        for (int ks = 0; ks < 4; ks++) {
            uint32_t ra[2][4];
#pragma unroll
            for (int mi = 0; mi < 2; mi++) {
                const int r = wm * 32 + mi * 16 + (lane & 15);
                const int ck = ks * 2 + (lane >> 4);
                LDSM_X4(ra[mi], Ab + SWZ(r * 128 + ck * 16));
            }
            uint32_t rb[4][4];
#pragma unroll
            for (int g = 0; g < 4; g++) {
                const int nr = wn * 64 + g * 16 + ((lane & 7) | ((lane & 16) >> 1));
                const int ck = ks * 2 + ((lane >> 3) & 1);
                LDSM_X4(rb[g], Bb + SWZ(nr * 128 + ck * 16));
            }
#pragma unroll
            for (int mi = 0; mi < 2; mi++)
#pragma unroll
                for (int g = 0; g < 4; g++) {
                    MMA16816(acc[mi][2 * g + 0], ra[mi], rb[g][0], rb[g][1]);
                    MMA16816(acc[mi][2 * g + 1], ra[mi], rb[g][2], rb[g][3]);
                }
        }
        if (it + 1 < NIT) __syncthreads();
    }

    const OutDesc od = outs.d[z];
#pragma unroll
    for (int mi = 0; mi < 2; mi++) {
        const int r0e = row0 + wm * 32 + mi * 16 + (lane >> 2);
#pragma unroll
        for (int ni = 0; ni < 8; ni++) {
            const int cl = wn * 64 + ni * 8 + (lane & 3) * 2;
            float b0 = 0.f, b1 = 0.f;
            if (od.bias) { b0 = od.bias[cl]; b1 = od.bias[cl + 1]; }
#pragma unroll
            for (int hrow = 0; hrow < 2; hrow++) {
                const int row = r0e + hrow * 8;
                if (row >= M) continue;
                float v0 = acc[mi][ni][2 * hrow + 0] + b0;
                float v1 = acc[mi][ni][2 * hrow + 1] + b1;
                if (od.mode == 0) {
                    float2 v = { v0, v1 };
                    *(float2*)((float*)od.C + (size_t)row * od.ldc + cl) = v;
                } else {
                    __half2 hv = __floats2half2_rn(v0, v1);
                    size_t pos;
                    if (od.mode == 1)
                        pos = (size_t)row * od.ldc + cl;
                    else
                        pos = (size_t)row * 256 + ((cl >> 2) * 8) + (cl & 3)
                              + (od.mode == 3 ? 4 : 0);
                    *(__half2*)((__half*)od.C + pos) = hv;
                }
            }
        }
    }
}

// ---------------------------------------------------------------------------
// conversions / weight prep
// ---------------------------------------------------------------------------
__global__ void cvt_k(const float* __restrict__ s, __half* __restrict__ d, long n) {
    long i = ((long)blockIdx.x * blockDim.x + threadIdx.x) * 4;
    if (i >= n) return;
    float4 v = *(const float4*)(s + i);
    *(__half2*)(d + i)     = __floats2half2_rn(v.x, v.y);
    *(__half2*)(d + i + 2) = __floats2half2_rn(v.z, v.w);
}

__global__ void prepw_k(const float* __restrict__ Wrel, const float* __restrict__ Wroot,
                        const float* __restrict__ Wq, const float* __restrict__ Wk,
                        const float* __restrict__ Wv, const float* __restrict__ Ws) {
    const int T0 = 9 * GD * HD;
    const int T1 = T0 + 4 * HD * HD;
    int i = blockIdx.x * blockDim.x + threadIdx.x;
    if (i >= T1) return;
    if (i < T0) {
        int z = i >> 16, rem = i & 65535;
        int k = rem >> 7, n = rem & 127;
        float v = (z < 8) ? Wrel[(long)z * 65536 + k * 128 + n] : Wroot[k * 128 + n];
        g_Wall[(long)z * 65536 + n * 512 + k] = __float2half(v);
    } else {
        int j = i - T0;
        int m = j >> 14, jj = j & 16383;
        int k = jj >> 7, n = jj & 127;
        float v = (m == 0) ? Wq[jj] : (m == 1) ? Wk[jj] : (m == 2) ? Wv[jj] : Ws[jj];
        __half h = __float2half_rn(v);
        long idx = (long)m * 16384 + n * 128 + k;
        g_Wqk_hi[idx] = h;
        g_Wqk_lo[idx] = __float2half_rn(v - __half2float(h));
    }
}

// ---------------------------------------------------------------------------
// index handling, counts, CSR build
// ---------------------------------------------------------------------------
__device__ __forceinline__ int ldidx(const void* p, long i) {
    return g_idx64 ? (int)((const long long*)p)[i] : ((const int*)p)[i];
}

__global__ void detect_k(const unsigned* __restrict__ w) {
    if (blockIdx.x == 0 && threadIdx.x == 0) {
        int is64 = 1;
        for (int i = 0; i < 32; i++)
            if (w[2 * i + 1] != 0u) { is64 = 0; break; }
        g_idx64 = is64;
    }
}

__global__ void zero_k() {
    int i = blockIdx.x * blockDim.x + threadIdx.x;
    if (i < NN * RR) g_cnt[i] = 0;
    if (i < NN) g_fill[i] = 0;
    if (i < HD) { g_bnsum[i] = 0.f; g_bnsq[i] = 0.f; }
}

__global__ void count_k(const void* __restrict__ ei, const void* __restrict__ et) {
    int e = blockIdx.x * blockDim.x + threadIdx.x;
    if (e >= EE) return;
    int dst = ldidx(ei, (long)EE + e);
    int r   = ldidx(et, e);
    atomicAdd(&g_cnt[dst * RR + r], 1);
}

__global__ void degsum_k() {
    int i = blockIdx.x * blockDim.x + threadIdx.x;
    if (i >= NN) return;
    int d = 0;
#pragma unroll
    for (int r = 0; r < RR; r++) d += g_cnt[i * RR + r];
    g_deg[i] = d;
}

__global__ void scanA_k() {
    __shared__ int s[256];
    int i = blockIdx.x * 256 + threadIdx.x;
    s[threadIdx.x] = (i < NN) ? g_deg[i] : 0;
    __syncthreads();
    for (int st = 128; st; st >>= 1) {
        if (threadIdx.x < st) s[threadIdx.x] += s[threadIdx.x + st];
        __syncthreads();
    }
    if (threadIdx.x == 0) g_bsum[blockIdx.x] = s[0];
}

__global__ void scanB_k() {
    __shared__ int s[256];
    int v = (threadIdx.x < NBS) ? g_bsum[threadIdx.x] : 0;
    s[threadIdx.x] = v;
    __syncthreads();
    for (int st = 1; st < 256; st <<= 1) {
        int t = (threadIdx.x >= st) ? s[threadIdx.x - st] : 0;
        __syncthreads();
        s[threadIdx.x] += t;
        __syncthreads();
    }
    if (threadIdx.x < NBS) g_bsumx[threadIdx.x] = s[threadIdx.x] - v;
}

__global__ void scanC_k() {
    __shared__ int s[256];
    int i = blockIdx.x * 256 + threadIdx.x;
    int v = (i < NN) ? g_deg[i] : 0;
    s[threadIdx.x] = v;
    __syncthreads();
    for (int st = 1; st < 256; st <<= 1) {
        int t = (threadIdx.x >= st) ? s[threadIdx.x - st] : 0;
        __syncthreads();
        s[threadIdx.x] += t;
        __syncthreads();
    }
    if (i < NN) g_off[i] = g_bsumx[blockIdx.x] + s[threadIdx.x] - v;
}

__global__ void bucket_k(const void* __restrict__ ei, const void* __restrict__ et) {
    int e = blockIdx.x * blockDim.x + threadIdx.x;
    if (e >= EE) return;
    int src = ldidx(ei, e);
    int dst = ldidx(ei, (long)EE + e);
    int r   = ldidx(et, e);
    int pos = g_off[dst] + atomicAdd(&g_fill[dst], 1);
    g_csr[pos] = (unsigned)src | ((unsigned)r << 24);
}

// ---------------------------------------------------------------------------
// warp-per-dst RGCN aggregation (fp16 gather, 4-edge unroll) + fused h split
// ---------------------------------------------------------------------------
__global__ void agg1csr_k() {
    int dst = (blockIdx.x * blockDim.x + threadIdx.x) >> 5;
    int lane = threadIdx.x & 31;
    if (dst >= NN) return;
    float invc = 0.f;
    if (lane < RR) {
        int c = g_cnt[dst * RR + lane];
        invc = 1.0f / (float)max(c, 1);
    }
    const int off = g_off[dst], deg = g_deg[dst];
    float4 acc = {0.f, 0.f, 0.f, 0.f};
    for (int base = 0; base < deg; base += 32) {
        unsigned pk = 0;
        int m = min(32, deg - base);
        if (lane < m) pk = g_csr[off + base + lane];
        int j = 0;
        for (; j + 4 <= m; j += 4) {
            long s[4]; float w[4]; uint2 mv[4];
#pragma unroll
            for (int u = 0; u < 4; u++) {
                unsigned p = __shfl_sync(0xffffffffu, pk, j + u);
                s[u] = (long)(p & 0xFFFFFF);
                int r = p >> 24;
                w[u] = __shfl_sync(0xffffffffu, invc, r);
                mv[u] = *(const uint2*)(g_xWh + s[u] * 1024 + r * 128 + lane * 4);
            }
#pragma unroll
            for (int u = 0; u < 4; u++) {
                float2 a = __half22float2(*(__half2*)&mv[u].x);
                float2 b = __half22float2(*(__half2*)&mv[u].y);
                acc.x += w[u] * a.x; acc.y += w[u] * a.y;
                acc.z += w[u] * b.x; acc.w += w[u] * b.y;
            }
        }
        for (; j < m; j++) {
            unsigned p = __shfl_sync(0xffffffffu, pk, j);
            long s0 = (long)(p & 0xFFFFFF);
            int r0 = p >> 24;
            float w0 = __shfl_sync(0xffffffffu, invc, r0);
            uint2 m0 = *(const uint2*)(g_xWh + s0 * 1024 + r0 * 128 + lane * 4);
            float2 a0 = __half22float2(*(__half2*)&m0.x);
            float2 b0 = __half22float2(*(__half2*)&m0.y);
            acc.x += w0 * a0.x; acc.y += w0 * a0.y;
            acc.z += w0 * b0.x; acc.w += w0 * b0.y;
        }
    }
    float4 cur = g_h[(long)dst * 32 + lane];
    cur.x += acc.x; cur.y += acc.y; cur.z += acc.z; cur.w += acc.w;
    // fused fp16 hi/lo split of h for the 3-pass qkvs GEMM
    __half hx = __float2half_rn(cur.x), hy = __float2half_rn(cur.y);
    __half hz = __float2half_rn(cur.z), hw = __float2half_rn(cur.w);
    __half2* hp = (__half2*)(g_Hh + (size_t)dst * HD + lane * 4);
    hp[0] = __half2{hx, hy}; hp[1] = __half2{hz, hw};
    __half2* lp = (__half2*)(g_Hl + (size_t)dst * HD + lane * 4);
    lp[0] = __floats2half2_rn(cur.x - __half2float(hx), cur.y - __half2float(hy));
    lp[1] = __floats2half2_rn(cur.z - __half2float(hz), cur.w - __half2float(hw));
}

// ---------------------------------------------------------------------------
// warp-per-dst fused attention (4-edge unroll) + fused BN statistics.
// grid covers NN*32 threads exactly (50000*32 % 256 == 0): no partial blocks.
// ---------------------------------------------------------------------------
__global__ void attn_k(float* __restrict__ out) {
    __shared__ float sbn[HD], sbq[HD];
    const int tid = threadIdx.x;
    if (tid < HD) { sbn[tid] = 0.f; sbq[tid] = 0.f; }
    __syncthreads();

    int dst = (blockIdx.x * blockDim.x + tid) >> 5;
    int lane = tid & 31;
    const float4 qv = g_q[(long)dst * 32 + lane];
    const int off = g_off[dst], deg = g_deg[dst];
    float4 accv = {0.f, 0.f, 0.f, 0.f};
    float ssum = 0.f;
    const float sc = 0.08838834764831845f;  // 1/sqrt(128)
    for (int base = 0; base < deg; base += 32) {
        unsigned pk = 0;
        int m = min(32, deg - base);
        if (lane < m) pk = g_csr[off + base + lane];
        int j = 0;
        for (; j + 4 <= m; j += 4) {
            uint4 r[4]; float d[4];
#pragma unroll
            for (int u = 0; u < 4; u++) {
                unsigned p = __shfl_sync(0xffffffffu, pk, j + u);
                r[u] = *(const uint4*)(g_kvh + (long)(p & 0xFFFFFF) * 256 + lane * 8);
            }
#pragma unroll
            for (int u = 0; u < 4; u++) {
                float2 ka = __half22float2(*(__half2*)&r[u].x);
                float2 kb = __half22float2(*(__half2*)&r[u].y);
                d[u] = qv.x * ka.x + qv.y * ka.y + qv.z * kb.x + qv.w * kb.y;
            }
#pragma unroll
            for (int o = 16; o; o >>= 1) {
#pragma unroll
                for (int u = 0; u < 4; u++)
                    d[u] += __shfl_xor_sync(0xffffffffu, d[u], o);
            }
#pragma unroll
            for (int u = 0; u < 4; u++) {
                float e = expf(d[u] * sc);
                float2 va = __half22float2(*(__half2*)&r[u].z);
                float2 vb = __half22float2(*(__half2*)&r[u].w);
                ssum += e;
                accv.x += e * va.x; accv.y += e * va.y;
                accv.z += e * vb.x; accv.w += e * vb.y;
            }
        }
        for (; j < m; j++) {
            unsigned p = __shfl_sync(0xffffffffu, pk, j);
            uint4 r0 = *(const uint4*)(g_kvh + (long)(p & 0xFFFFFF) * 256 + lane * 8);
            float2 ka = __half22float2(*(__half2*)&r0.x);
            float2 kb = __half22float2(*(__half2*)&r0.y);
            float d0 = qv.x * ka.x + qv.y * ka.y + qv.z * kb.x + qv.w * kb.y;
#pragma unroll
            for (int o = 16; o; o >>= 1) d0 += __shfl_xor_sync(0xffffffffu, d0, o);
            float e = expf(d0 * sc);
            float2 va = __half22float2(*(__half2*)&r0.z);
            float2 vb = __half22float2(*(__half2*)&r0.w);
            ssum += e;
            accv.x += e * va.x; accv.y += e * va.y;
            accv.z += e * vb.x; accv.w += e * vb.y;
        }
    }
    float inv = 1.0f / fmaxf(ssum, 1e-16f);
    float4* op = (float4*)(out + (long)dst * 128) + lane;
    float4 cur = *op;
    cur.x += accv.x * inv; cur.y += accv.y * inv;
    cur.z += accv.z * inv; cur.w += accv.w * inv;
    *op = cur;

    // fused BN stats: each out row is produced by exactly one warp
    atomicAdd(&sbn[lane * 4 + 0], cur.x);
    atomicAdd(&sbn[lane * 4 + 1], cur.y);
    atomicAdd(&sbn[lane * 4 + 2], cur.z);
    atomicAdd(&sbn[lane * 4 + 3], cur.w);
    atomicAdd(&sbq[lane * 4 + 0], cur.x * cur.x);
    atomicAdd(&sbq[lane * 4 + 1], cur.y * cur.y);
    atomicAdd(&sbq[lane * 4 + 2], cur.z * cur.z);
    atomicAdd(&sbq[lane * 4 + 3], cur.w * cur.w);
    __syncthreads();
    if (tid < HD) {
        atomicAdd(&g_bnsum[tid], sbn[tid]);
        atomicAdd(&g_bnsq[tid], sbq[tid]);
    }
}

// ---------------------------------------------------------------------------
// batch norm finalize + apply
// ---------------------------------------------------------------------------
__global__ void bnfinal_k(const float* __restrict__ gamma, const float* __restrict__ beta) {
    int c = threadIdx.x;
    float mu  = g_bnsum[c] * (1.0f / NN);
    float var = g_bnsq[c] * (1.0f / NN) - mu * mu;
    var = fmaxf(var, 0.f);
    float inv = 1.0f / sqrtf(var + 1e-5f);
    float scv = gamma[c] * inv;
    g_scale[c] = scv;
    g_shift[c] = beta[c] - mu * scv;
}

__global__ void bnapply_k(float* __restrict__ out) {
    long i = (long)blockIdx.x * blockDim.x + threadIdx.x;
    int c = (int)(i & 127);
    float y = out[i] * g_scale[c] + g_shift[c];
    out[i] = (y >= 0.f) ? y : 0.01f * y;
}

// ---------------------------------------------------------------------------
extern "C" void kernel_launch(void* const* d_in, const int* in_sizes, int n_in,
                              void* d_out, int out_size)
{
    const float* x      = (const float*)d_in[0];
    const void*  ei     = d_in[1];
    const void*  et     = d_in[2];
    const float* W_rel  = (const float*)d_in[3];
    const float* W_root = (const float*)d_in[4];
    const float* b1     = (const float*)d_in[5];
    const float* Wq     = (const float*)d_in[6];
    const float* bq     = (const float*)d_in[7];
    const float* Wk     = (const float*)d_in[8];
    const float* bk     = (const float*)d_in[9];
    const float* Wv     = (const float*)d_in[10];
    const float* bv     = (const float*)d_in[11];
    const float* Wskip  = (const float*)d_in[12];
    const float* bskip  = (const float*)d_in[13];
    const float* gamma  = (const float*)d_in[14];
    const float* beta   = (const float*)d_in[15];
    float* out = (float*)d_out;

    void *xwhp, *hp, *qp, *kvp, *ahp, *hhp, *hlp, *wallp, *wqhp, *wqlp;
    cudaGetSymbolAddress(&xwhp, g_xWh);
    cudaGetSymbolAddress(&hp,  g_h);
    cudaGetSymbolAddress(&qp,  g_q);
    cudaGetSymbolAddress(&kvp, g_kvh);
    cudaGetSymbolAddress(&ahp, g_Ah);
    cudaGetSymbolAddress(&hhp, g_Hh);
    cudaGetSymbolAddress(&hlp, g_Hl);
    cudaGetSymbolAddress(&wallp, g_Wall);
    cudaGetSymbolAddress(&wqhp, g_Wqk_hi);
    cudaGetSymbolAddress(&wqlp, g_Wqk_lo);

    const int SMEM_BYTES = 3 * 32768;
    cudaFuncSetAttribute(mmagemm_k<1>, cudaFuncAttributeMaxDynamicSharedMemorySize, SMEM_BYTES);
    cudaFuncSetAttribute(mmagemm_k<3>, cudaFuncAttributeMaxDynamicSharedMemorySize, SMEM_BYTES);

    const int rowTiles = (NN + 127) / 128;  // 391

    detect_k<<<1, 32>>>((const unsigned*)ei);
    zero_k<<<(NN * RR + 255) / 256, 256>>>();
    count_k<<<(EE + 255) / 256, 256>>>(ei, et);
    prepw_k<<<(9 * GD * HD + 4 * HD * HD + 255) / 256, 256>>>(
        W_rel, W_root, Wq, Wk, Wv, Wskip);
    cvt_k<<<(int)(((long)NN * GD / 4 + 255) / 256), 256>>>(
        x, (__half*)ahp, (long)NN * GD);

    // CSR by dst
    degsum_k<<<(NN + 255) / 256, 256>>>();
    scanA_k<<<NBS, 256>>>();
    scanB_k<<<1, 256>>>();
    scanC_k<<<NBS, 256>>>();
    bucket_k<<<(EE + 255) / 256, 256>>>(ei, et);

    // GEMM1 (single-pass fp16): z<8 -> xW fp16 (ldc 1024 halves); z=8 -> h f32
    OutPack p1{};
    for (int zz = 0; zz < 8; zz++)
        p1.d[zz] = { (void*)((__half*)xwhp + zz * 128), nullptr, 1024, 1 };
    p1.d[8] = { hp, b1, (long)HD, 0 };
    mmagemm_k<1><<<dim3(9, rowTiles), 256, SMEM_BYTES>>>(
        (const __half*)ahp, nullptr, (const __half*)wallp, nullptr,
        p1, NN, GD, (long)HD * GD);

    // RGCN mean aggregation (fp16 gather, 4-edge unroll) + fused h hi/lo split
    agg1csr_k<<<(NN * 32 + 255) / 256, 256>>>();

    // GEMM2 (3-pass fp16 split): q f32, k/v fp16 interleaved, skip -> out f32
    OutPack p2{};
    p2.d[0] = { qp,  bq,    (long)HD, 0 };
    p2.d[1] = { kvp, bk,    256,      2 };
    p2.d[2] = { kvp, bv,    256,      3 };
    p2.d[3] = { out, bskip, (long)HD, 0 };
    mmagemm_k<3><<<dim3(4, rowTiles), 256, SMEM_BYTES>>>(
        (const __half*)hhp, (const __half*)hlp,
        (const __half*)wqhp, (const __half*)wqlp,
        p2, NN, HD, (long)HD * HD);

    // fused attention + BN stats (atomic-free output, 4-edge unroll)
    attn_k<<<(NN * 32) / 256, 256>>>(out);

    // batch norm finalize + apply (in-place on out)
    bnfinal_k<<<1, HD>>>(gamma, beta);
    bnapply_k<<<(NN * HD) / 256, 256>>>(out);
}